// round 1
// baseline (speedup 1.0000x reference)
#include <cuda_runtime.h>
#include <math.h>

// Problem constants
#define BB   4
#define SS   2048
#define DD   256
#define HH   8
#define DKH  32
#define RH   64          // RANK*H
#define DFFC 1024
#define MM   (BB*SS)     // 8192 rows

// ---------------- scratch (no allocs allowed) ----------------
__device__ float g_qd [MM*RH];
__device__ float g_kd [MM*RH];
__device__ float g_Q  [MM*DD];
__device__ float g_K  [MM*DD];
__device__ float g_V  [MM*DD];
__device__ float g_ctx[MM*DD];
__device__ float g_ao [MM*DD];
__device__ float g_ln1[MM*DD];
__device__ float g_h  [MM*DFFC];
__device__ float g_ff [MM*DD];

// ---------------- fused GEMM: Y[M,N] = X[M,K] @ W[N,K]^T + b, opt GELU ----------------
// BM=BN=64, BK=16, 256 threads, 4x4 per thread. All dims divisible.
__device__ __forceinline__ float gelu_exact(float x) {
    return 0.5f * x * (1.0f + erff(x * 0.70710678118654752f));
}

template<int ACT>
__global__ __launch_bounds__(256)
void gemm_bias(const float* __restrict__ X, const float* __restrict__ W,
               const float* __restrict__ bias, float* __restrict__ Y,
               int Mdim, int Ndim, int Kdim) {
    const int BM = 64, BN = 64, BK = 16;
    __shared__ float As[BK][BM + 1];
    __shared__ float Bs[BK][BN + 1];
    const int tid  = threadIdx.x;
    const int tx   = tid & 15;        // 16 cols of threads
    const int ty   = tid >> 4;        // 16 rows of threads
    const int brow = blockIdx.y * BM;
    const int bcol = blockIdx.x * BN;

    float acc[4][4] = {};

    for (int k0 = 0; k0 < Kdim; k0 += BK) {
        #pragma unroll
        for (int i = tid; i < BM * BK; i += 256) {
            int r = i >> 4, c = i & 15;
            As[c][r] = X[(size_t)(brow + r) * Kdim + k0 + c];
        }
        #pragma unroll
        for (int i = tid; i < BN * BK; i += 256) {
            int r = i >> 4, c = i & 15;
            Bs[c][r] = W[(size_t)(bcol + r) * Kdim + k0 + c];
        }
        __syncthreads();

        #pragma unroll
        for (int kk = 0; kk < BK; kk++) {
            float a[4], bv[4];
            #pragma unroll
            for (int i = 0; i < 4; i++) a[i]  = As[kk][ty * 4 + i];
            #pragma unroll
            for (int j = 0; j < 4; j++) bv[j] = Bs[kk][tx * 4 + j];
            #pragma unroll
            for (int i = 0; i < 4; i++)
                #pragma unroll
                for (int j = 0; j < 4; j++)
                    acc[i][j] = fmaf(a[i], bv[j], acc[i][j]);
        }
        __syncthreads();
    }

    #pragma unroll
    for (int i = 0; i < 4; i++) {
        int r = brow + ty * 4 + i;
        #pragma unroll
        for (int j = 0; j < 4; j++) {
            int c = bcol + tx * 4 + j;
            float v = acc[i][j] + bias[c];
            if (ACT == 1) v = gelu_exact(v);
            Y[(size_t)r * Ndim + c] = v;
        }
    }
}

// ---------------- flash attention (fp32, online softmax) ----------------
// grid: (S/64, H, B), 256 threads. Q pre-scaled by 1/sqrt(DK).
// Layout: Q/K/V/O are [B,S,D], head h = cols [h*32, h*32+32).
__global__ __launch_bounds__(256)
void flash_attn(const float* __restrict__ Q, const float* __restrict__ K,
                const float* __restrict__ V, float* __restrict__ O) {
    const int BQ = 64, BKEY = 64;
    const int qt = blockIdx.x, h = blockIdx.y, b = blockIdx.z;
    const int tid = threadIdx.x;
    const int tx = tid & 15, ty = tid >> 4;
    const float scale = 0.1767766952966369f; // 1/sqrt(32)

    __shared__ float Qs[DKH][BQ];
    __shared__ float Ks[DKH][BKEY];
    __shared__ float Vs[BKEY][DKH];
    __shared__ float Ps[BQ][BKEY + 1];
    __shared__ float red[BQ][17];
    __shared__ float m_sh[BQ], l_sh[BQ];

    const float* Qb = Q + ((size_t)b * SS + (size_t)qt * BQ) * DD + h * DKH;
    const float* Kb = K + (size_t)b * SS * DD + h * DKH;
    const float* Vb = V + (size_t)b * SS * DD + h * DKH;
    float*       Ob = O + ((size_t)b * SS + (size_t)qt * BQ) * DD + h * DKH;

    #pragma unroll
    for (int i = tid; i < BQ * DKH; i += 256) {
        int r = i >> 5, d = i & 31;
        Qs[d][r] = Qb[(size_t)r * DD + d] * scale;
    }
    if (tid < BQ) { m_sh[tid] = -INFINITY; l_sh[tid] = 0.0f; }

    float acc[4][2] = {};  // O[ty*4+i][tx*2+j]

    for (int kt = 0; kt < SS / BKEY; kt++) {
        __syncthreads();  // protect Qs (first iter) + Ps/Ks/Vs reuse
        #pragma unroll
        for (int i = tid; i < BKEY * DKH; i += 256) {
            int r = i >> 5, d = i & 31;
            size_t goff = (size_t)(kt * BKEY + r) * DD + d;
            Ks[d][r] = Kb[goff];
            Vs[r][d] = Vb[goff];
        }
        __syncthreads();

        // scores (already scaled via Q)
        float s[4][4] = {};
        #pragma unroll
        for (int d = 0; d < DKH; d++) {
            float a[4], bb[4];
            #pragma unroll
            for (int i = 0; i < 4; i++) a[i]  = Qs[d][ty * 4 + i];
            #pragma unroll
            for (int j = 0; j < 4; j++) bb[j] = Ks[d][tx * 4 + j];
            #pragma unroll
            for (int i = 0; i < 4; i++)
                #pragma unroll
                for (int j = 0; j < 4; j++)
                    s[i][j] = fmaf(a[i], bb[j], s[i][j]);
        }

        // local row max -> red
        #pragma unroll
        for (int i = 0; i < 4; i++) {
            float mx = s[i][0];
            #pragma unroll
            for (int j = 1; j < 4; j++) mx = fmaxf(mx, s[i][j]);
            red[ty * 4 + i][tx] = mx;
        }
        __syncthreads();

        float mold[4], mnew[4], alpha[4], rsum[4], p[4][4];
        #pragma unroll
        for (int i = 0; i < 4; i++) {
            int row = ty * 4 + i;
            mold[i] = m_sh[row];
            float mt = red[row][0];
            #pragma unroll
            for (int t = 1; t < 16; t++) mt = fmaxf(mt, red[row][t]);
            mnew[i]  = fmaxf(mold[i], mt);
            alpha[i] = __expf(mold[i] - mnew[i]);
            rsum[i] = 0.0f;
            #pragma unroll
            for (int j = 0; j < 4; j++) {
                p[i][j] = __expf(s[i][j] - mnew[i]);
                rsum[i] += p[i][j];
            }
        }
        __syncthreads();  // everyone done reading red/m_sh

        #pragma unroll
        for (int i = 0; i < 4; i++) {
            red[ty * 4 + i][tx] = rsum[i];
            #pragma unroll
            for (int j = 0; j < 4; j++) Ps[ty * 4 + i][tx * 4 + j] = p[i][j];
            acc[i][0] *= alpha[i];
            acc[i][1] *= alpha[i];
        }
        __syncthreads();  // Ps + red(sum) visible

        if (tx == 0) {
            #pragma unroll
            for (int i = 0; i < 4; i++) {
                int row = ty * 4 + i;
                float lt = 0.0f;
                #pragma unroll
                for (int t = 0; t < 16; t++) lt += red[row][t];
                l_sh[row] = l_sh[row] * alpha[i] + lt;
                m_sh[row] = mnew[i];
            }
        }

        // O accumulate: acc[i][j] += sum_kk Ps[row][kk] * Vs[kk][tx*2+j]
        #pragma unroll 4
        for (int kk = 0; kk < BKEY; kk++) {
            float pv[4], vv[2];
            vv[0] = Vs[kk][tx * 2 + 0];
            vv[1] = Vs[kk][tx * 2 + 1];
            #pragma unroll
            for (int i = 0; i < 4; i++) pv[i] = Ps[ty * 4 + i][kk];
            #pragma unroll
            for (int i = 0; i < 4; i++) {
                acc[i][0] = fmaf(pv[i], vv[0], acc[i][0]);
                acc[i][1] = fmaf(pv[i], vv[1], acc[i][1]);
            }
        }
    }
    __syncthreads();

    #pragma unroll
    for (int i = 0; i < 4; i++) {
        int row = ty * 4 + i;
        float inv_l = 1.0f / l_sh[row];
        Ob[(size_t)row * DD + tx * 2 + 0] = acc[i][0] * inv_l;
        Ob[(size_t)row * DD + tx * 2 + 1] = acc[i][1] * inv_l;
    }
}

// ---------------- fused residual + LayerNorm (warp per row, D=256) ----------------
__global__ __launch_bounds__(256)
void ln_residual(const float* __restrict__ X, const float* __restrict__ R,
                 const float* __restrict__ g, const float* __restrict__ bta,
                 float* __restrict__ Y) {
    int row  = blockIdx.x * 8 + (threadIdx.x >> 5);
    int lane = threadIdx.x & 31;
    const float* xr = X + (size_t)row * DD;
    const float* rr = R + (size_t)row * DD;

    float v[8];
    float sum = 0.0f;
    #pragma unroll
    for (int k = 0; k < 8; k++) {
        v[k] = xr[lane + 32 * k] + rr[lane + 32 * k];
        sum += v[k];
    }
    #pragma unroll
    for (int o = 16; o > 0; o >>= 1) sum += __shfl_xor_sync(0xffffffffu, sum, o);
    float mu = sum * (1.0f / 256.0f);

    float vs = 0.0f;
    #pragma unroll
    for (int k = 0; k < 8; k++) { float d = v[k] - mu; vs = fmaf(d, d, vs); }
    #pragma unroll
    for (int o = 16; o > 0; o >>= 1) vs += __shfl_xor_sync(0xffffffffu, vs, o);
    float rstd = rsqrtf(vs * (1.0f / 256.0f) + 1e-5f);

    #pragma unroll
    for (int k = 0; k < 8; k++) {
        int c = lane + 32 * k;
        Y[(size_t)row * DD + c] = (v[k] - mu) * rstd * g[c] + bta[c];
    }
}

// ---------------- launch ----------------
extern "C" void kernel_launch(void* const* d_in, const int* in_sizes, int n_in,
                              void* d_out, int out_size) {
    const float* x       = (const float*)d_in[0];
    const float* Wq_down = (const float*)d_in[1];
    const float* bq_down = (const float*)d_in[2];
    const float* Wq_up   = (const float*)d_in[3];
    const float* bq_up   = (const float*)d_in[4];
    const float* Wk_down = (const float*)d_in[5];
    const float* bk_down = (const float*)d_in[6];
    const float* Wk_up   = (const float*)d_in[7];
    const float* bk_up   = (const float*)d_in[8];
    const float* Wv      = (const float*)d_in[9];
    const float* bv      = (const float*)d_in[10];
    const float* Wo      = (const float*)d_in[11];
    const float* bo      = (const float*)d_in[12];
    const float* ln_a_g  = (const float*)d_in[13];
    const float* ln_a_b  = (const float*)d_in[14];
    const float* W_ff1   = (const float*)d_in[15];
    const float* b_ff1   = (const float*)d_in[16];
    const float* W_ff2   = (const float*)d_in[17];
    const float* b_ff2   = (const float*)d_in[18];
    const float* ln_b_g  = (const float*)d_in[19];
    const float* ln_b_b  = (const float*)d_in[20];
    float* out = (float*)d_out;

    float *qd, *kd, *Qm, *Km, *Vm, *ctx, *ao, *ln1, *hb, *ff;
    cudaGetSymbolAddress((void**)&qd,  g_qd);
    cudaGetSymbolAddress((void**)&kd,  g_kd);
    cudaGetSymbolAddress((void**)&Qm,  g_Q);
    cudaGetSymbolAddress((void**)&Km,  g_K);
    cudaGetSymbolAddress((void**)&Vm,  g_V);
    cudaGetSymbolAddress((void**)&ctx, g_ctx);
    cudaGetSymbolAddress((void**)&ao,  g_ao);
    cudaGetSymbolAddress((void**)&ln1, g_ln1);
    cudaGetSymbolAddress((void**)&hb,  g_h);
    cudaGetSymbolAddress((void**)&ff,  g_ff);

    dim3 thr(256);
    // Low-rank Q/K down (M=8192, N=64, K=256) and up (M=8192, N=256, K=64)
    gemm_bias<0><<<dim3(RH / 64,  MM / 64), thr>>>(x,  Wq_down, bq_down, qd, MM, RH, DD);
    gemm_bias<0><<<dim3(RH / 64,  MM / 64), thr>>>(x,  Wk_down, bk_down, kd, MM, RH, DD);
    gemm_bias<0><<<dim3(DD / 64,  MM / 64), thr>>>(qd, Wq_up,   bq_up,   Qm, MM, DD, RH);
    gemm_bias<0><<<dim3(DD / 64,  MM / 64), thr>>>(kd, Wk_up,   bk_up,   Km, MM, DD, RH);
    // V projection
    gemm_bias<0><<<dim3(DD / 64,  MM / 64), thr>>>(x,  Wv,      bv,      Vm, MM, DD, DD);
    // Attention
    flash_attn<<<dim3(SS / 64, HH, BB), thr>>>(Qm, Km, Vm, ctx);
    // Output projection
    gemm_bias<0><<<dim3(DD / 64,  MM / 64), thr>>>(ctx, Wo,     bo,      ao, MM, DD, DD);
    // LN(x + attn_out)
    ln_residual<<<MM / 8, thr>>>(x, ao, ln_a_g, ln_a_b, ln1);
    // FFN
    gemm_bias<1><<<dim3(DFFC / 64, MM / 64), thr>>>(ln1, W_ff1, b_ff1, hb, MM, DFFC, DD);
    gemm_bias<0><<<dim3(DD / 64,   MM / 64), thr>>>(hb,  W_ff2, b_ff2, ff, MM, DD, DFFC);
    // Final LN(ln1 + ff)
    ln_residual<<<MM / 8, thr>>>(ln1, ff, ln_b_g, ln_b_b, out);
}

// round 2
// speedup vs baseline: 3.3450x; 3.3450x over previous
#include <cuda_runtime.h>
#include <math.h>
#include <stdint.h>

// Problem constants
#define BB   4
#define SS   2048
#define DD   256
#define HH   8
#define DKH  32
#define RH   64          // RANK*H
#define DFFC 1024
#define MM   (BB*SS)     // 8192 rows

// ---------------- scratch (no allocs allowed) ----------------
__device__ float g_qd [MM*RH];
__device__ float g_kd [MM*RH];
__device__ float g_Q  [MM*DD];
__device__ float g_K  [MM*DD];
__device__ float g_V  [MM*DD];
__device__ float g_ctx[MM*DD];
__device__ float g_ao [MM*DD];
__device__ float g_ln1[MM*DD];
__device__ float g_h  [MM*DFFC];
__device__ float g_ff [MM*DD];

// ---------------- tf32 helpers ----------------
__device__ __forceinline__ uint32_t f2tf(float x) {
    uint32_t u; asm("cvt.rna.tf32.f32 %0, %1;" : "=r"(u) : "f"(x)); return u;
}
__device__ __forceinline__ void mma_tf32(float* c, uint32_t a0, uint32_t a1,
                                         uint32_t a2, uint32_t a3,
                                         uint32_t b0, uint32_t b1) {
    asm volatile(
        "mma.sync.aligned.m16n8k8.row.col.f32.tf32.tf32.f32 "
        "{%0,%1,%2,%3},{%4,%5,%6,%7},{%8,%9},{%0,%1,%2,%3};"
        : "+f"(c[0]), "+f"(c[1]), "+f"(c[2]), "+f"(c[3])
        : "r"(a0), "r"(a1), "r"(a2), "r"(a3), "r"(b0), "r"(b1));
}
__device__ __forceinline__ float gelu_exact(float x) {
    return 0.5f * x * (1.0f + erff(x * 0.70710678118654752f));
}

// ---------------- tf32 GEMM: Y[M,N] = X[M,K] @ W[N,K]^T + b, opt GELU ----------------
// BM=128, BN=64, BK=32, 256 threads (8 warps, 4m x 2n), warp tile 32x32.
#define GBM 128
#define GBN 64
#define GBK 32
#define ASTR 36

template<int ACT>
__global__ __launch_bounds__(256)
void gemm_tf32(const float* __restrict__ X, const float* __restrict__ W,
               const float* __restrict__ bias, float* __restrict__ Y,
               int Ndim, int Kdim) {
    __shared__ uint32_t As[GBM][ASTR];
    __shared__ uint32_t Bs[GBN][ASTR];
    const int tid  = threadIdx.x;
    const int lane = tid & 31, w = tid >> 5;
    const int wm = w >> 1, wn = w & 1;
    const int g = lane >> 2, t = lane & 3;
    const int brow = blockIdx.y * GBM;
    const int bcol = blockIdx.x * GBN;

    float acc[2][4][4] = {};

    for (int k0 = 0; k0 < Kdim; k0 += GBK) {
        #pragma unroll
        for (int i = 0; i < 4; i++) {
            int idx = tid + 256 * i;
            int r = idx >> 3, c4 = (idx & 7) << 2;
            const float4 v = *(const float4*)&X[(size_t)(brow + r) * Kdim + k0 + c4];
            As[r][c4 + 0] = f2tf(v.x); As[r][c4 + 1] = f2tf(v.y);
            As[r][c4 + 2] = f2tf(v.z); As[r][c4 + 3] = f2tf(v.w);
        }
        #pragma unroll
        for (int i = 0; i < 2; i++) {
            int idx = tid + 256 * i;
            int r = idx >> 3, c4 = (idx & 7) << 2;
            const float4 v = *(const float4*)&W[(size_t)(bcol + r) * Kdim + k0 + c4];
            Bs[r][c4 + 0] = f2tf(v.x); Bs[r][c4 + 1] = f2tf(v.y);
            Bs[r][c4 + 2] = f2tf(v.z); Bs[r][c4 + 3] = f2tf(v.w);
        }
        __syncthreads();

        #pragma unroll
        for (int kk = 0; kk < GBK; kk += 8) {
            uint32_t a[2][4], b[4][2];
            #pragma unroll
            for (int i = 0; i < 2; i++) {
                int rb = wm * 32 + i * 16;
                a[i][0] = As[rb + g    ][kk + t];
                a[i][1] = As[rb + g + 8][kk + t];
                a[i][2] = As[rb + g    ][kk + t + 4];
                a[i][3] = As[rb + g + 8][kk + t + 4];
            }
            #pragma unroll
            for (int j = 0; j < 4; j++) {
                int cb = wn * 32 + j * 8 + g;
                b[j][0] = Bs[cb][kk + t];
                b[j][1] = Bs[cb][kk + t + 4];
            }
            #pragma unroll
            for (int i = 0; i < 2; i++)
                #pragma unroll
                for (int j = 0; j < 4; j++)
                    mma_tf32(acc[i][j], a[i][0], a[i][1], a[i][2], a[i][3],
                             b[j][0], b[j][1]);
        }
        __syncthreads();
    }

    #pragma unroll
    for (int i = 0; i < 2; i++) {
        int r0 = brow + wm * 32 + i * 16 + g;
        #pragma unroll
        for (int j = 0; j < 4; j++) {
            int col = bcol + wn * 32 + j * 8 + 2 * t;
            float b0 = bias[col], b1 = bias[col + 1];
            float v00 = acc[i][j][0] + b0, v01 = acc[i][j][1] + b1;
            float v10 = acc[i][j][2] + b0, v11 = acc[i][j][3] + b1;
            if (ACT) { v00 = gelu_exact(v00); v01 = gelu_exact(v01);
                       v10 = gelu_exact(v10); v11 = gelu_exact(v11); }
            Y[(size_t)r0 * Ndim + col]           = v00;
            Y[(size_t)r0 * Ndim + col + 1]       = v01;
            Y[(size_t)(r0 + 8) * Ndim + col]     = v10;
            Y[(size_t)(r0 + 8) * Ndim + col + 1] = v11;
        }
    }
}

// ---------------- flash attention with tf32 MMA ----------------
// BQ=64, BKEY=64, DK=32. 8 warps: S phase warp = 16q x 32key (4 n-tiles);
// PV phase warp = 16q x 16d (2 n-tiles). Online softmax state in shared.
#define AQ 64
#define AK 64

__global__ __launch_bounds__(256)
void flash_attn_mma(const float* __restrict__ Q, const float* __restrict__ K,
                    const float* __restrict__ V, float* __restrict__ O) {
    __shared__ uint32_t Qs[AQ][36];
    __shared__ uint32_t Ks[AK][36];
    __shared__ uint32_t Vst[DKH][68];   // V transposed: [d][key]
    __shared__ uint32_t Ps[AQ][68];
    __shared__ float rowred[2][AQ];
    __shared__ float m_sh[AQ], l_sh[AQ];

    const int qt = blockIdx.x, h = blockIdx.y, b = blockIdx.z;
    const int tid = threadIdx.x, lane = tid & 31, w = tid >> 5;
    const int wm = w >> 1, wn = w & 1;
    const int g = lane >> 2, t = lane & 3;
    const float scale = 0.17677669529663687f;  // 1/sqrt(32)

    const float* Qb = Q + ((size_t)b * SS + (size_t)qt * AQ) * DD + h * DKH;
    const float* Kb = K + (size_t)b * SS * DD + h * DKH;
    const float* Vb = V + (size_t)b * SS * DD + h * DKH;
    float*       Ob = O + ((size_t)b * SS + (size_t)qt * AQ) * DD + h * DKH;

    // Load + scale Q tile (64x32): 512 float4 / 256 threads = 2 each
    #pragma unroll
    for (int i = 0; i < 2; i++) {
        int idx = tid + 256 * i;
        int r = idx >> 3, c4 = (idx & 7) << 2;
        const float4 v = *(const float4*)&Qb[(size_t)r * DD + c4];
        Qs[r][c4 + 0] = f2tf(v.x * scale); Qs[r][c4 + 1] = f2tf(v.y * scale);
        Qs[r][c4 + 2] = f2tf(v.z * scale); Qs[r][c4 + 3] = f2tf(v.w * scale);
    }
    if (tid < AQ) { m_sh[tid] = -1e30f; l_sh[tid] = 0.0f; }

    const int r0 = wm * 16 + g, r1 = r0 + 8;
    float acc_o[2][4] = {};

    for (int kt = 0; kt < SS / AK; kt++) {
        __syncthreads();  // Ks/Vst/Ps safe to overwrite; m/l updates visible
        #pragma unroll
        for (int i = 0; i < 2; i++) {
            int idx = tid + 256 * i;
            int r = idx >> 3, c4 = (idx & 7) << 2;
            size_t go = (size_t)(kt * AK + r) * DD + c4;
            const float4 kv = *(const float4*)&Kb[go];
            Ks[r][c4 + 0] = f2tf(kv.x); Ks[r][c4 + 1] = f2tf(kv.y);
            Ks[r][c4 + 2] = f2tf(kv.z); Ks[r][c4 + 3] = f2tf(kv.w);
            const float4 vv = *(const float4*)&Vb[go];
            Vst[c4 + 0][r] = f2tf(vv.x); Vst[c4 + 1][r] = f2tf(vv.y);
            Vst[c4 + 2][r] = f2tf(vv.z); Vst[c4 + 3][r] = f2tf(vv.w);
        }
        __syncthreads();

        // S = Q K^T  (warp: rows wm*16..+15, cols wn*32..+31)
        float s[4][4] = {};
        #pragma unroll
        for (int kk = 0; kk < DKH; kk += 8) {
            uint32_t a0 = Qs[r0][kk + t],     a1 = Qs[r1][kk + t];
            uint32_t a2 = Qs[r0][kk + t + 4], a3 = Qs[r1][kk + t + 4];
            #pragma unroll
            for (int j = 0; j < 4; j++) {
                int cb = wn * 32 + j * 8 + g;
                mma_tf32(s[j], a0, a1, a2, a3, Ks[cb][kk + t], Ks[cb][kk + t + 4]);
            }
        }

        // row max (warp-local 32 keys)
        float mx0 = -1e30f, mx1 = -1e30f;
        #pragma unroll
        for (int j = 0; j < 4; j++) {
            mx0 = fmaxf(mx0, fmaxf(s[j][0], s[j][1]));
            mx1 = fmaxf(mx1, fmaxf(s[j][2], s[j][3]));
        }
        mx0 = fmaxf(mx0, __shfl_xor_sync(0xffffffffu, mx0, 1));
        mx0 = fmaxf(mx0, __shfl_xor_sync(0xffffffffu, mx0, 2));
        mx1 = fmaxf(mx1, __shfl_xor_sync(0xffffffffu, mx1, 1));
        mx1 = fmaxf(mx1, __shfl_xor_sync(0xffffffffu, mx1, 2));
        if (t == 0) { rowred[wn][r0] = mx0; rowred[wn][r1] = mx1; }
        __syncthreads();

        float mt0 = fmaxf(rowred[0][r0], rowred[1][r0]);
        float mt1 = fmaxf(rowred[0][r1], rowred[1][r1]);
        float mo0 = m_sh[r0], mo1 = m_sh[r1];
        float mn0 = fmaxf(mo0, mt0), mn1 = fmaxf(mo1, mt1);
        float al0 = __expf(mo0 - mn0), al1 = __expf(mo1 - mn1);

        float sum0 = 0.0f, sum1 = 0.0f;
        #pragma unroll
        for (int j = 0; j < 4; j++) {
            s[j][0] = __expf(s[j][0] - mn0); s[j][1] = __expf(s[j][1] - mn0);
            s[j][2] = __expf(s[j][2] - mn1); s[j][3] = __expf(s[j][3] - mn1);
            sum0 += s[j][0] + s[j][1];
            sum1 += s[j][2] + s[j][3];
            int cb = wn * 32 + j * 8 + 2 * t;
            Ps[r0][cb]     = f2tf(s[j][0]); Ps[r0][cb + 1] = f2tf(s[j][1]);
            Ps[r1][cb]     = f2tf(s[j][2]); Ps[r1][cb + 1] = f2tf(s[j][3]);
        }
        sum0 += __shfl_xor_sync(0xffffffffu, sum0, 1);
        sum0 += __shfl_xor_sync(0xffffffffu, sum0, 2);
        sum1 += __shfl_xor_sync(0xffffffffu, sum1, 1);
        sum1 += __shfl_xor_sync(0xffffffffu, sum1, 2);
        if (t == 0) { rowred[wn][r0] = sum0; rowred[wn][r1] = sum1; }
        __syncthreads();

        // single updater per row (wn==0, t==0 covers all 64 rows)
        if (wn == 0 && t == 0) {
            l_sh[r0] = l_sh[r0] * al0 + rowred[0][r0] + rowred[1][r0];
            l_sh[r1] = l_sh[r1] * al1 + rowred[0][r1] + rowred[1][r1];
            m_sh[r0] = mn0; m_sh[r1] = mn1;
        }

        // PV: rescale then accumulate (warp: rows r0/r1, cols wn*16..+15)
        #pragma unroll
        for (int j = 0; j < 2; j++) {
            acc_o[j][0] *= al0; acc_o[j][1] *= al0;
            acc_o[j][2] *= al1; acc_o[j][3] *= al1;
        }
        #pragma unroll
        for (int kk = 0; kk < AK; kk += 8) {
            uint32_t a0 = Ps[r0][kk + t],     a1 = Ps[r1][kk + t];
            uint32_t a2 = Ps[r0][kk + t + 4], a3 = Ps[r1][kk + t + 4];
            #pragma unroll
            for (int j = 0; j < 2; j++) {
                int cb = wn * 16 + j * 8 + g;
                mma_tf32(acc_o[j], a0, a1, a2, a3,
                         Vst[cb][kk + t], Vst[cb][kk + t + 4]);
            }
        }
    }
    __syncthreads();

    const float il0 = 1.0f / l_sh[r0];
    const float il1 = 1.0f / l_sh[r1];
    #pragma unroll
    for (int j = 0; j < 2; j++) {
        int col = wn * 16 + j * 8 + 2 * t;
        Ob[(size_t)r0 * DD + col]     = acc_o[j][0] * il0;
        Ob[(size_t)r0 * DD + col + 1] = acc_o[j][1] * il0;
        Ob[(size_t)r1 * DD + col]     = acc_o[j][2] * il1;
        Ob[(size_t)r1 * DD + col + 1] = acc_o[j][3] * il1;
    }
}

// ---------------- fused residual + LayerNorm (warp per row, D=256) ----------------
__global__ __launch_bounds__(256)
void ln_residual(const float* __restrict__ X, const float* __restrict__ R,
                 const float* __restrict__ g, const float* __restrict__ bta,
                 float* __restrict__ Y) {
    int row  = blockIdx.x * 8 + (threadIdx.x >> 5);
    int lane = threadIdx.x & 31;
    const float* xr = X + (size_t)row * DD;
    const float* rr = R + (size_t)row * DD;

    float v[8];
    float sum = 0.0f;
    #pragma unroll
    for (int k = 0; k < 8; k++) {
        v[k] = xr[lane + 32 * k] + rr[lane + 32 * k];
        sum += v[k];
    }
    #pragma unroll
    for (int o = 16; o > 0; o >>= 1) sum += __shfl_xor_sync(0xffffffffu, sum, o);
    float mu = sum * (1.0f / 256.0f);

    float vs = 0.0f;
    #pragma unroll
    for (int k = 0; k < 8; k++) { float d = v[k] - mu; vs = fmaf(d, d, vs); }
    #pragma unroll
    for (int o = 16; o > 0; o >>= 1) vs += __shfl_xor_sync(0xffffffffu, vs, o);
    float rstd = rsqrtf(vs * (1.0f / 256.0f) + 1e-5f);

    #pragma unroll
    for (int k = 0; k < 8; k++) {
        int c = lane + 32 * k;
        Y[(size_t)row * DD + c] = (v[k] - mu) * rstd * g[c] + bta[c];
    }
}

// ---------------- launch ----------------
extern "C" void kernel_launch(void* const* d_in, const int* in_sizes, int n_in,
                              void* d_out, int out_size) {
    const float* x       = (const float*)d_in[0];
    const float* Wq_down = (const float*)d_in[1];
    const float* bq_down = (const float*)d_in[2];
    const float* Wq_up   = (const float*)d_in[3];
    const float* bq_up   = (const float*)d_in[4];
    const float* Wk_down = (const float*)d_in[5];
    const float* bk_down = (const float*)d_in[6];
    const float* Wk_up   = (const float*)d_in[7];
    const float* bk_up   = (const float*)d_in[8];
    const float* Wv      = (const float*)d_in[9];
    const float* bv      = (const float*)d_in[10];
    const float* Wo      = (const float*)d_in[11];
    const float* bo      = (const float*)d_in[12];
    const float* ln_a_g  = (const float*)d_in[13];
    const float* ln_a_b  = (const float*)d_in[14];
    const float* W_ff1   = (const float*)d_in[15];
    const float* b_ff1   = (const float*)d_in[16];
    const float* W_ff2   = (const float*)d_in[17];
    const float* b_ff2   = (const float*)d_in[18];
    const float* ln_b_g  = (const float*)d_in[19];
    const float* ln_b_b  = (const float*)d_in[20];
    float* out = (float*)d_out;

    float *qd, *kd, *Qm, *Km, *Vm, *ctx, *ao, *ln1, *hb, *ff;
    cudaGetSymbolAddress((void**)&qd,  g_qd);
    cudaGetSymbolAddress((void**)&kd,  g_kd);
    cudaGetSymbolAddress((void**)&Qm,  g_Q);
    cudaGetSymbolAddress((void**)&Km,  g_K);
    cudaGetSymbolAddress((void**)&Vm,  g_V);
    cudaGetSymbolAddress((void**)&ctx, g_ctx);
    cudaGetSymbolAddress((void**)&ao,  g_ao);
    cudaGetSymbolAddress((void**)&ln1, g_ln1);
    cudaGetSymbolAddress((void**)&hb,  g_h);
    cudaGetSymbolAddress((void**)&ff,  g_ff);

    dim3 thr(256);
    // Low-rank Q/K down (N=64, K=256) and up (N=256, K=64)
    gemm_tf32<0><<<dim3(RH / GBN,  MM / GBM), thr>>>(x,  Wq_down, bq_down, qd, RH, DD);
    gemm_tf32<0><<<dim3(RH / GBN,  MM / GBM), thr>>>(x,  Wk_down, bk_down, kd, RH, DD);
    gemm_tf32<0><<<dim3(DD / GBN,  MM / GBM), thr>>>(qd, Wq_up,   bq_up,   Qm, DD, RH);
    gemm_tf32<0><<<dim3(DD / GBN,  MM / GBM), thr>>>(kd, Wk_up,   bk_up,   Km, DD, RH);
    // V projection
    gemm_tf32<0><<<dim3(DD / GBN,  MM / GBM), thr>>>(x,  Wv,      bv,      Vm, DD, DD);
    // Attention
    flash_attn_mma<<<dim3(SS / AQ, HH, BB), thr>>>(Qm, Km, Vm, ctx);
    // Output projection
    gemm_tf32<0><<<dim3(DD / GBN,  MM / GBM), thr>>>(ctx, Wo,     bo,      ao, DD, DD);
    // LN(x + attn_out)
    ln_residual<<<MM / 8, thr>>>(x, ao, ln_a_g, ln_a_b, ln1);
    // FFN
    gemm_tf32<1><<<dim3(DFFC / GBN, MM / GBM), thr>>>(ln1, W_ff1, b_ff1, hb, DFFC, DD);
    gemm_tf32<0><<<dim3(DD / GBN,   MM / GBM), thr>>>(hb,  W_ff2, b_ff2, ff, DD, DFFC);
    // Final LN(ln1 + ff)
    ln_residual<<<MM / 8, thr>>>(ln1, ff, ln_b_g, ln_b_b, out);
}

// round 3
// speedup vs baseline: 3.9473x; 1.1801x over previous
#include <cuda_runtime.h>
#include <math.h>
#include <stdint.h>

// Problem constants
#define BB   4
#define SS   2048
#define DD   256
#define HH   8
#define DKH  32
#define RH   64          // RANK*H
#define DFFC 1024
#define MM   (BB*SS)     // 8192 rows

// ---------------- scratch (no allocs allowed) ----------------
__device__ float g_qd [MM*RH];
__device__ float g_kd [MM*RH];
__device__ float g_Q  [MM*DD];
__device__ float g_K  [MM*DD];
__device__ float g_V  [MM*DD];
__device__ float g_ctx[MM*DD];
__device__ float g_ao [MM*DD];
__device__ float g_ln1[MM*DD];
__device__ float g_h  [MM*DFFC];
__device__ float g_ff [MM*DD];

// ---------------- helpers ----------------
__device__ __forceinline__ uint32_t sptr(const void* p) {
    return (uint32_t)__cvta_generic_to_shared(p);
}
__device__ __forceinline__ void cp16(uint32_t s, const void* g) {
    asm volatile("cp.async.cg.shared.global [%0], [%1], 16;\n" :: "r"(s), "l"(g));
}
__device__ __forceinline__ void cpcommit() {
    asm volatile("cp.async.commit_group;\n" ::: "memory");
}
template<int N> __device__ __forceinline__ void cpwait() {
    asm volatile("cp.async.wait_group %0;\n" :: "n"(N) : "memory");
}
__device__ __forceinline__ void mma_tf32(float* c, uint32_t a0, uint32_t a1,
                                         uint32_t a2, uint32_t a3,
                                         uint32_t b0, uint32_t b1) {
    asm volatile(
        "mma.sync.aligned.m16n8k8.row.col.f32.tf32.tf32.f32 "
        "{%0,%1,%2,%3},{%4,%5,%6,%7},{%8,%9},{%0,%1,%2,%3};"
        : "+f"(c[0]), "+f"(c[1]), "+f"(c[2]), "+f"(c[3])
        : "r"(a0), "r"(a1), "r"(a2), "r"(a3), "r"(b0), "r"(b1));
}
__device__ __forceinline__ float gelu_exact(float x) {
    return 0.5f * x * (1.0f + erff(x * 0.70710678118654752f));
}
#define UF(x) __float_as_uint(x)

// ---------------- tf32 GEMM: Y[M,N] = X[M,K] @ W[N,K]^T + b, opt GELU ----------------
// BM=128, BN=64, BK=32, 256 threads (8 warps, 4m x 2n), warp tile 32x32.
// Double-buffered cp.async, raw-fp32-as-tf32 operands.
#define GBM 128
#define GBN 64
#define GBK 32
#define KST 40          // padded smem row stride (floats); 8t+g conflict-free
#define GEMM_SMEM (2 * (GBM + GBN) * KST * 4)

template<int ACT>
__global__ __launch_bounds__(256)
void gemm_tf32(const float* __restrict__ X, const float* __restrict__ W,
               const float* __restrict__ bias, float* __restrict__ Y,
               int Ndim, int Kdim) {
    extern __shared__ float sm[];
    float* As = sm;                      // [2][GBM][KST]
    float* Bs = sm + 2 * GBM * KST;      // [2][GBN][KST]

    const int tid  = threadIdx.x;
    const int lane = tid & 31, w = tid >> 5;
    const int wm = w >> 1, wn = w & 1;
    const int g = lane >> 2, t = lane & 3;
    const int brow = blockIdx.y * GBM;
    const int bcol = blockIdx.x * GBN;
    const int nk = Kdim / GBK;

    // prologue: prefetch tile 0 into buf 0
    {
        #pragma unroll
        for (int i = 0; i < 4; i++) {
            int idx = tid + 256 * i;
            int r = idx >> 3, c = (idx & 7) * 4;
            cp16(sptr(&As[r * KST + c]), &X[(size_t)(brow + r) * Kdim + c]);
        }
        #pragma unroll
        for (int i = 0; i < 2; i++) {
            int idx = tid + 256 * i;
            int r = idx >> 3, c = (idx & 7) * 4;
            cp16(sptr(&Bs[r * KST + c]), &W[(size_t)(bcol + r) * Kdim + c]);
        }
        cpcommit();
    }

    float acc[2][4][4] = {};

    for (int k = 0; k < nk; k++) {
        cpwait<0>();
        __syncthreads();
        if (k + 1 < nk) {
            int k0 = (k + 1) * GBK;
            float* Ad = As + ((k + 1) & 1) * GBM * KST;
            float* Bd = Bs + ((k + 1) & 1) * GBN * KST;
            #pragma unroll
            for (int i = 0; i < 4; i++) {
                int idx = tid + 256 * i;
                int r = idx >> 3, c = (idx & 7) * 4;
                cp16(sptr(&Ad[r * KST + c]), &X[(size_t)(brow + r) * Kdim + k0 + c]);
            }
            #pragma unroll
            for (int i = 0; i < 2; i++) {
                int idx = tid + 256 * i;
                int r = idx >> 3, c = (idx & 7) * 4;
                cp16(sptr(&Bd[r * KST + c]), &W[(size_t)(bcol + r) * Kdim + k0 + c]);
            }
            cpcommit();
        }
        const float* Ac = As + (k & 1) * GBM * KST;
        const float* Bc = Bs + (k & 1) * GBN * KST;

        #pragma unroll
        for (int ks = 0; ks < GBK / 8; ks++) {
            int kk = ks * 8;
            uint32_t a[2][4], b[4][2];
            #pragma unroll
            for (int i = 0; i < 2; i++) {
                int rb = wm * 32 + i * 16;
                a[i][0] = UF(Ac[(rb + g    ) * KST + kk + t]);
                a[i][1] = UF(Ac[(rb + g + 8) * KST + kk + t]);
                a[i][2] = UF(Ac[(rb + g    ) * KST + kk + t + 4]);
                a[i][3] = UF(Ac[(rb + g + 8) * KST + kk + t + 4]);
            }
            #pragma unroll
            for (int j = 0; j < 4; j++) {
                int cb = wn * 32 + j * 8 + g;
                b[j][0] = UF(Bc[cb * KST + kk + t]);
                b[j][1] = UF(Bc[cb * KST + kk + t + 4]);
            }
            #pragma unroll
            for (int i = 0; i < 2; i++)
                #pragma unroll
                for (int j = 0; j < 4; j++)
                    mma_tf32(acc[i][j], a[i][0], a[i][1], a[i][2], a[i][3],
                             b[j][0], b[j][1]);
        }
    }

    #pragma unroll
    for (int i = 0; i < 2; i++) {
        int r0 = brow + wm * 32 + i * 16 + g;
        #pragma unroll
        for (int j = 0; j < 4; j++) {
            int col = bcol + wn * 32 + j * 8 + 2 * t;
            float b0 = bias[col], b1 = bias[col + 1];
            float v00 = acc[i][j][0] + b0, v01 = acc[i][j][1] + b1;
            float v10 = acc[i][j][2] + b0, v11 = acc[i][j][3] + b1;
            if (ACT) { v00 = gelu_exact(v00); v01 = gelu_exact(v01);
                       v10 = gelu_exact(v10); v11 = gelu_exact(v11); }
            *(float2*)&Y[(size_t)r0 * Ndim + col]       = make_float2(v00, v01);
            *(float2*)&Y[(size_t)(r0 + 8) * Ndim + col] = make_float2(v10, v11);
        }
    }
}

// ---------------- flash attention, warp-owns-rows, double-buffered ----------------
// BQ=128 (8 warps x 16 rows), BKEY=64, DK=32. Softmax fully warp-local.
#define PST 68          // P smem stride (floats); 4g+t conflict-free reads
#define ATTN_SMEM ((4 * 64 * KST + 128 * PST) * 4)
#define NKT (SS / 64)

__global__ __launch_bounds__(256)
void flash_attn_mma(const float* __restrict__ Q, const float* __restrict__ K,
                    const float* __restrict__ V, float* __restrict__ O) {
    extern __shared__ float sm[];
    float* Ks = sm;                      // [2][64][KST]
    float* Vs = sm + 2 * 64 * KST;       // [2][64][KST]  (row-major [key][d])
    float* Ps = sm + 4 * 64 * KST;       // [128][PST]   (also Q staging)

    const int qt = blockIdx.x, h = blockIdx.y, b = blockIdx.z;
    const int tid = threadIdx.x, lane = tid & 31, w = tid >> 5;
    const int g = lane >> 2, t = lane & 3;
    const float scale = 0.17677669529663687f;  // 1/sqrt(32)

    const float* Qb = Q + ((size_t)b * SS + (size_t)qt * 128) * DD + h * DKH;
    const float* Kb = K + (size_t)b * SS * DD + h * DKH;
    const float* Vb = V + (size_t)b * SS * DD + h * DKH;
    float*       Ob = O + ((size_t)b * SS + (size_t)qt * 128) * DD + h * DKH;

    // stage Q (128x32) into Ps region + prefetch K/V tile 0 into buf 0
    #pragma unroll
    for (int i = 0; i < 4; i++) {
        int idx = tid + 256 * i;
        int r = idx >> 3, c = (idx & 7) * 4;
        cp16(sptr(&Ps[r * PST + c]), &Qb[(size_t)r * DD + c]);
    }
    #pragma unroll
    for (int i = 0; i < 2; i++) {
        int idx = tid + 256 * i;
        int r = idx >> 3, c = (idx & 7) * 4;
        cp16(sptr(&Ks[r * KST + c]), &Kb[(size_t)r * DD + c]);
        cp16(sptr(&Vs[r * KST + c]), &Vb[(size_t)r * DD + c]);
    }
    cpcommit();
    cpwait<0>();
    __syncthreads();

    // hoist Q fragments (scaled) into registers for the whole loop
    const int r0 = w * 16 + g, r1 = r0 + 8;
    uint32_t qa[4][4];
    #pragma unroll
    for (int ks = 0; ks < 4; ks++) {
        int kk = ks * 8;
        qa[ks][0] = UF(Ps[r0 * PST + kk + t]     * scale);
        qa[ks][1] = UF(Ps[r1 * PST + kk + t]     * scale);
        qa[ks][2] = UF(Ps[r0 * PST + kk + t + 4] * scale);
        qa[ks][3] = UF(Ps[r1 * PST + kk + t + 4] * scale);
    }
    __syncthreads();   // all Q reads done before Ps is overwritten with P

    float m0 = -1e30f, m1 = -1e30f, l0 = 0.0f, l1 = 0.0f;
    float acc[4][4] = {};

    for (int kt = 0; kt < NKT; kt++) {
        cpwait<0>();
        __syncthreads();
        if (kt + 1 < NKT) {
            const float* Kn = Kb + (size_t)(kt + 1) * 64 * DD;
            const float* Vn = Vb + (size_t)(kt + 1) * 64 * DD;
            float* Kd = Ks + ((kt + 1) & 1) * 64 * KST;
            float* Vd = Vs + ((kt + 1) & 1) * 64 * KST;
            #pragma unroll
            for (int i = 0; i < 2; i++) {
                int idx = tid + 256 * i;
                int r = idx >> 3, c = (idx & 7) * 4;
                cp16(sptr(&Kd[r * KST + c]), &Kn[(size_t)r * DD + c]);
                cp16(sptr(&Vd[r * KST + c]), &Vn[(size_t)r * DD + c]);
            }
            cpcommit();
        }
        const float* Kc = Ks + (kt & 1) * 64 * KST;
        const float* Vc = Vs + (kt & 1) * 64 * KST;

        // S = Q K^T : warp rows r0/r1, all 64 keys (8 n-tiles)
        float s[8][4] = {};
        #pragma unroll
        for (int ks = 0; ks < 4; ks++) {
            int kk = ks * 8;
            #pragma unroll
            for (int j = 0; j < 8; j++) {
                int cb = j * 8 + g;
                mma_tf32(s[j], qa[ks][0], qa[ks][1], qa[ks][2], qa[ks][3],
                         UF(Kc[cb * KST + kk + t]), UF(Kc[cb * KST + kk + t + 4]));
            }
        }

        // warp-local online softmax (rows r0, r1)
        float mx0 = -1e30f, mx1 = -1e30f;
        #pragma unroll
        for (int j = 0; j < 8; j++) {
            mx0 = fmaxf(mx0, fmaxf(s[j][0], s[j][1]));
            mx1 = fmaxf(mx1, fmaxf(s[j][2], s[j][3]));
        }
        mx0 = fmaxf(mx0, __shfl_xor_sync(0xffffffffu, mx0, 1));
        mx0 = fmaxf(mx0, __shfl_xor_sync(0xffffffffu, mx0, 2));
        mx1 = fmaxf(mx1, __shfl_xor_sync(0xffffffffu, mx1, 1));
        mx1 = fmaxf(mx1, __shfl_xor_sync(0xffffffffu, mx1, 2));
        float mn0 = fmaxf(m0, mx0), mn1 = fmaxf(m1, mx1);
        float al0 = __expf(m0 - mn0), al1 = __expf(m1 - mn1);
        m0 = mn0; m1 = mn1;

        float sum0 = 0.0f, sum1 = 0.0f;
        #pragma unroll
        for (int j = 0; j < 8; j++) {
            float p0 = __expf(s[j][0] - mn0), p1 = __expf(s[j][1] - mn0);
            float p2 = __expf(s[j][2] - mn1), p3 = __expf(s[j][3] - mn1);
            sum0 += p0 + p1; sum1 += p2 + p3;
            *(float2*)&Ps[r0 * PST + j * 8 + 2 * t] = make_float2(p0, p1);
            *(float2*)&Ps[r1 * PST + j * 8 + 2 * t] = make_float2(p2, p3);
        }
        sum0 += __shfl_xor_sync(0xffffffffu, sum0, 1);
        sum0 += __shfl_xor_sync(0xffffffffu, sum0, 2);
        sum1 += __shfl_xor_sync(0xffffffffu, sum1, 1);
        sum1 += __shfl_xor_sync(0xffffffffu, sum1, 2);
        l0 = l0 * al0 + sum0;
        l1 = l1 * al1 + sum1;

        #pragma unroll
        for (int j = 0; j < 4; j++) {
            acc[j][0] *= al0; acc[j][1] *= al0;
            acc[j][2] *= al1; acc[j][3] *= al1;
        }
        __syncwarp();   // P stores visible to sibling lanes before PV reads

        // PV: O[r, d] += P[r, key] * V[key, d]  (b-frag straight from [key][d])
        #pragma unroll
        for (int ks = 0; ks < 8; ks++) {
            int kk = ks * 8;
            uint32_t a0 = UF(Ps[r0 * PST + kk + t]);
            uint32_t a1 = UF(Ps[r1 * PST + kk + t]);
            uint32_t a2 = UF(Ps[r0 * PST + kk + t + 4]);
            uint32_t a3 = UF(Ps[r1 * PST + kk + t + 4]);
            #pragma unroll
            for (int j = 0; j < 4; j++) {
                int cb = j * 8 + g;
                mma_tf32(acc[j], a0, a1, a2, a3,
                         UF(Vc[(kk + t) * KST + cb]), UF(Vc[(kk + t + 4) * KST + cb]));
            }
        }
    }

    const float il0 = 1.0f / l0, il1 = 1.0f / l1;
    #pragma unroll
    for (int j = 0; j < 4; j++) {
        int col = j * 8 + 2 * t;
        *(float2*)&Ob[(size_t)r0 * DD + col] = make_float2(acc[j][0] * il0, acc[j][1] * il0);
        *(float2*)&Ob[(size_t)r1 * DD + col] = make_float2(acc[j][2] * il1, acc[j][3] * il1);
    }
}

// ---------------- fused residual + LayerNorm (warp per row, D=256, float4) ----------------
__global__ __launch_bounds__(256)
void ln_residual(const float* __restrict__ X, const float* __restrict__ R,
                 const float* __restrict__ g, const float* __restrict__ bta,
                 float* __restrict__ Y) {
    int row  = blockIdx.x * 8 + (threadIdx.x >> 5);
    int lane = threadIdx.x & 31;
    const float4* x4 = (const float4*)(X + (size_t)row * DD);
    const float4* r4 = (const float4*)(R + (size_t)row * DD);

    float4 v[2];
    float sum = 0.0f;
    #pragma unroll
    for (int k = 0; k < 2; k++) {
        float4 a = x4[lane + 32 * k], b = r4[lane + 32 * k];
        v[k] = make_float4(a.x + b.x, a.y + b.y, a.z + b.z, a.w + b.w);
        sum += v[k].x + v[k].y + v[k].z + v[k].w;
    }
    #pragma unroll
    for (int o = 16; o > 0; o >>= 1) sum += __shfl_xor_sync(0xffffffffu, sum, o);
    float mu = sum * (1.0f / 256.0f);

    float vs = 0.0f;
    #pragma unroll
    for (int k = 0; k < 2; k++) {
        float dx = v[k].x - mu, dy = v[k].y - mu, dz = v[k].z - mu, dw = v[k].w - mu;
        vs = fmaf(dx, dx, vs); vs = fmaf(dy, dy, vs);
        vs = fmaf(dz, dz, vs); vs = fmaf(dw, dw, vs);
    }
    #pragma unroll
    for (int o = 16; o > 0; o >>= 1) vs += __shfl_xor_sync(0xffffffffu, vs, o);
    float rstd = rsqrtf(vs * (1.0f / 256.0f) + 1e-5f);

    const float4* g4 = (const float4*)g;
    const float4* b4 = (const float4*)bta;
    float4* y4 = (float4*)(Y + (size_t)row * DD);
    #pragma unroll
    for (int k = 0; k < 2; k++) {
        float4 gg = g4[lane + 32 * k], bb = b4[lane + 32 * k];
        float4 o;
        o.x = (v[k].x - mu) * rstd * gg.x + bb.x;
        o.y = (v[k].y - mu) * rstd * gg.y + bb.y;
        o.z = (v[k].z - mu) * rstd * gg.z + bb.z;
        o.w = (v[k].w - mu) * rstd * gg.w + bb.w;
        y4[lane + 32 * k] = o;
    }
}

// ---------------- launch ----------------
extern "C" void kernel_launch(void* const* d_in, const int* in_sizes, int n_in,
                              void* d_out, int out_size) {
    const float* x       = (const float*)d_in[0];
    const float* Wq_down = (const float*)d_in[1];
    const float* bq_down = (const float*)d_in[2];
    const float* Wq_up   = (const float*)d_in[3];
    const float* bq_up   = (const float*)d_in[4];
    const float* Wk_down = (const float*)d_in[5];
    const float* bk_down = (const float*)d_in[6];
    const float* Wk_up   = (const float*)d_in[7];
    const float* bk_up   = (const float*)d_in[8];
    const float* Wv      = (const float*)d_in[9];
    const float* bv      = (const float*)d_in[10];
    const float* Wo      = (const float*)d_in[11];
    const float* bo      = (const float*)d_in[12];
    const float* ln_a_g  = (const float*)d_in[13];
    const float* ln_a_b  = (const float*)d_in[14];
    const float* W_ff1   = (const float*)d_in[15];
    const float* b_ff1   = (const float*)d_in[16];
    const float* W_ff2   = (const float*)d_in[17];
    const float* b_ff2   = (const float*)d_in[18];
    const float* ln_b_g  = (const float*)d_in[19];
    const float* ln_b_b  = (const float*)d_in[20];
    float* out = (float*)d_out;

    float *qd, *kd, *Qm, *Km, *Vm, *ctx, *ao, *ln1, *hb, *ff;
    cudaGetSymbolAddress((void**)&qd,  g_qd);
    cudaGetSymbolAddress((void**)&kd,  g_kd);
    cudaGetSymbolAddress((void**)&Qm,  g_Q);
    cudaGetSymbolAddress((void**)&Km,  g_K);
    cudaGetSymbolAddress((void**)&Vm,  g_V);
    cudaGetSymbolAddress((void**)&ctx, g_ctx);
    cudaGetSymbolAddress((void**)&ao,  g_ao);
    cudaGetSymbolAddress((void**)&ln1, g_ln1);
    cudaGetSymbolAddress((void**)&hb,  g_h);
    cudaGetSymbolAddress((void**)&ff,  g_ff);

    cudaFuncSetAttribute(gemm_tf32<0>, cudaFuncAttributeMaxDynamicSharedMemorySize, GEMM_SMEM);
    cudaFuncSetAttribute(gemm_tf32<1>, cudaFuncAttributeMaxDynamicSharedMemorySize, GEMM_SMEM);
    cudaFuncSetAttribute(flash_attn_mma, cudaFuncAttributeMaxDynamicSharedMemorySize, ATTN_SMEM);

    dim3 thr(256);
    gemm_tf32<0><<<dim3(RH / GBN,  MM / GBM), thr, GEMM_SMEM>>>(x,  Wq_down, bq_down, qd, RH, DD);
    gemm_tf32<0><<<dim3(RH / GBN,  MM / GBM), thr, GEMM_SMEM>>>(x,  Wk_down, bk_down, kd, RH, DD);
    gemm_tf32<0><<<dim3(DD / GBN,  MM / GBM), thr, GEMM_SMEM>>>(qd, Wq_up,   bq_up,   Qm, DD, RH);
    gemm_tf32<0><<<dim3(DD / GBN,  MM / GBM), thr, GEMM_SMEM>>>(kd, Wk_up,   bk_up,   Km, DD, RH);
    gemm_tf32<0><<<dim3(DD / GBN,  MM / GBM), thr, GEMM_SMEM>>>(x,  Wv,      bv,      Vm, DD, DD);
    flash_attn_mma<<<dim3(SS / 128, HH, BB), thr, ATTN_SMEM>>>(Qm, Km, Vm, ctx);
    gemm_tf32<0><<<dim3(DD / GBN,  MM / GBM), thr, GEMM_SMEM>>>(ctx, Wo,     bo,      ao, DD, DD);
    ln_residual<<<MM / 8, thr>>>(x, ao, ln_a_g, ln_a_b, ln1);
    gemm_tf32<1><<<dim3(DFFC / GBN, MM / GBM), thr, GEMM_SMEM>>>(ln1, W_ff1, b_ff1, hb, DFFC, DD);
    gemm_tf32<0><<<dim3(DD / GBN,   MM / GBM), thr, GEMM_SMEM>>>(hb,  W_ff2, b_ff2, ff, DD, DFFC);
    ln_residual<<<MM / 8, thr>>>(ln1, ff, ln_b_g, ln_b_b, out);
}

// round 4
// speedup vs baseline: 5.1453x; 1.3035x over previous
#include <cuda_runtime.h>
#include <math.h>
#include <stdint.h>

// Problem constants
#define BB   4
#define SS   2048
#define DD   256
#define HH   8
#define DKH  32
#define RH   64          // RANK*H
#define DFFC 1024
#define MM   (BB*SS)     // 8192 rows

// ---------------- scratch (no allocs allowed) ----------------
__device__ float g_qd [MM*RH];
__device__ float g_kd [MM*RH];
__device__ float g_Q  [MM*DD];
__device__ float g_K  [MM*DD];
__device__ float g_V  [MM*DD];
__device__ float g_ctx[MM*DD];
__device__ float g_ao [MM*DD];
__device__ float g_ln1[MM*DD];
__device__ float g_h  [MM*DFFC];
__device__ float g_ff [MM*DD];

// ---------------- helpers ----------------
__device__ __forceinline__ uint32_t sptr(const void* p) {
    return (uint32_t)__cvta_generic_to_shared(p);
}
__device__ __forceinline__ void cp16(uint32_t s, const void* g) {
    asm volatile("cp.async.cg.shared.global [%0], [%1], 16;\n" :: "r"(s), "l"(g));
}
__device__ __forceinline__ void cpcommit() {
    asm volatile("cp.async.commit_group;\n" ::: "memory");
}
template<int N> __device__ __forceinline__ void cpwait() {
    asm volatile("cp.async.wait_group %0;\n" :: "n"(N) : "memory");
}
// ldmatrix x4 (b16 view): for tf32, each 8x8 b16 matrix == 8x4 f32;
// lane L gets element (L/4, L%4) of matrix i in reg i — exact tf32 mma frag.
__device__ __forceinline__ void ldsm4(uint32_t* r, uint32_t addr) {
    asm volatile("ldmatrix.sync.aligned.m8n8.x4.shared.b16 {%0,%1,%2,%3}, [%4];"
                 : "=r"(r[0]), "=r"(r[1]), "=r"(r[2]), "=r"(r[3]) : "r"(addr));
}
__device__ __forceinline__ void mma_tf32(float* c, uint32_t a0, uint32_t a1,
                                         uint32_t a2, uint32_t a3,
                                         uint32_t b0, uint32_t b1) {
    asm volatile(
        "mma.sync.aligned.m16n8k8.row.col.f32.tf32.tf32.f32 "
        "{%0,%1,%2,%3},{%4,%5,%6,%7},{%8,%9},{%0,%1,%2,%3};"
        : "+f"(c[0]), "+f"(c[1]), "+f"(c[2]), "+f"(c[3])
        : "r"(a0), "r"(a1), "r"(a2), "r"(a3), "r"(b0), "r"(b1));
}
__device__ __forceinline__ float ex2(float x) {
    float r; asm("ex2.approx.f32 %0, %1;" : "=f"(r) : "f"(x)); return r;
}
__device__ __forceinline__ float gelu_exact(float x) {
    return 0.5f * x * (1.0f + erff(x * 0.70710678118654752f));
}
#define UF(x) __float_as_uint(x)

// ---------------- tf32 GEMM (dual): Y[M,N] = X[M,K] @ W[N,K]^T + b ----------------
// BM=128, BN=64, BK=32, 256 threads (8 warps, 4m x 2n), warp tile 32x32.
// blockIdx.z selects problem {0,1} (fused independent GEMMs of same shape).
#define GBM 128
#define GBN 64
#define GBK 32
#define KST 36          // smem row stride (words): 36%32=4 -> ldmatrix conflict-free
#define BOFF (2 * GBM * KST)
#define GEMM_SMEM (2 * (GBM + GBN) * KST * 4)

template<int ACT>
__global__ __launch_bounds__(256)
void gemm_tf32(const float* __restrict__ X0, const float* __restrict__ W0,
               const float* __restrict__ B0, float* __restrict__ Y0,
               const float* __restrict__ X1, const float* __restrict__ W1,
               const float* __restrict__ B1, float* __restrict__ Y1,
               int Ndim, int Kdim) {
    const float* X    = blockIdx.z ? X1 : X0;
    const float* W    = blockIdx.z ? W1 : W0;
    const float* bias = blockIdx.z ? B1 : B0;
    float*       Y    = blockIdx.z ? Y1 : Y0;

    extern __shared__ float sm[];
    const uint32_t sb = sptr(sm);

    const int tid  = threadIdx.x;
    const int lane = tid & 31, w = tid >> 5;
    const int wm = w >> 1, wn = w & 1;
    const int g = lane >> 2, t = lane & 3;
    const int m4 = lane >> 3, r8 = lane & 7;
    const int brow = blockIdx.y * GBM;
    const int bcol = blockIdx.x * GBN;
    const int nk = Kdim / GBK;

    // per-lane ldmatrix word offsets
    int offA0 = (wm * 32 + (m4 & 1) * 8 + r8) * KST + (m4 >> 1) * 4;
    int offA1 = offA0 + 16 * KST;
    int offB0 = BOFF + (wn * 32 + (m4 >> 1) * 8 + r8) * KST + (m4 & 1) * 4;
    int offB1 = offB0 + 16 * KST;

    // prologue: prefetch tile 0 into buf 0
    #pragma unroll
    for (int i = 0; i < 4; i++) {
        int idx = tid + 256 * i;
        int r = idx >> 3, c = (idx & 7) * 4;
        cp16(sb + (r * KST + c) * 4, &X[(size_t)(brow + r) * Kdim + c]);
    }
    #pragma unroll
    for (int i = 0; i < 2; i++) {
        int idx = tid + 256 * i;
        int r = idx >> 3, c = (idx & 7) * 4;
        cp16(sb + (BOFF + r * KST + c) * 4, &W[(size_t)(bcol + r) * Kdim + c]);
    }
    cpcommit();

    float acc[2][4][4] = {};

    for (int k = 0; k < nk; k++) {
        cpwait<0>();
        __syncthreads();
        if (k + 1 < nk) {
            int k0 = (k + 1) * GBK;
            int abuf = ((k + 1) & 1) * GBM * KST;
            int bbuf = BOFF + ((k + 1) & 1) * GBN * KST;
            #pragma unroll
            for (int i = 0; i < 4; i++) {
                int idx = tid + 256 * i;
                int r = idx >> 3, c = (idx & 7) * 4;
                cp16(sb + (abuf + r * KST + c) * 4, &X[(size_t)(brow + r) * Kdim + k0 + c]);
            }
            #pragma unroll
            for (int i = 0; i < 2; i++) {
                int idx = tid + 256 * i;
                int r = idx >> 3, c = (idx & 7) * 4;
                cp16(sb + (bbuf + r * KST + c) * 4, &W[(size_t)(bcol + r) * Kdim + k0 + c]);
            }
            cpcommit();
        }
        const int abuf = (k & 1) * GBM * KST;
        const int bbuf = (k & 1) * GBN * KST;

        #pragma unroll
        for (int ks = 0; ks < GBK / 8; ks++) {
            const int kk = ks * 8;
            uint32_t a0[4], a1[4], b0[4], b1[4];
            ldsm4(a0, sb + (abuf + offA0 + kk) * 4);
            ldsm4(a1, sb + (abuf + offA1 + kk) * 4);
            ldsm4(b0, sb + (bbuf + offB0 + kk) * 4);
            ldsm4(b1, sb + (bbuf + offB1 + kk) * 4);
            mma_tf32(acc[0][0], a0[0], a0[1], a0[2], a0[3], b0[0], b0[1]);
            mma_tf32(acc[0][1], a0[0], a0[1], a0[2], a0[3], b0[2], b0[3]);
            mma_tf32(acc[0][2], a0[0], a0[1], a0[2], a0[3], b1[0], b1[1]);
            mma_tf32(acc[0][3], a0[0], a0[1], a0[2], a0[3], b1[2], b1[3]);
            mma_tf32(acc[1][0], a1[0], a1[1], a1[2], a1[3], b0[0], b0[1]);
            mma_tf32(acc[1][1], a1[0], a1[1], a1[2], a1[3], b0[2], b0[3]);
            mma_tf32(acc[1][2], a1[0], a1[1], a1[2], a1[3], b1[0], b1[1]);
            mma_tf32(acc[1][3], a1[0], a1[1], a1[2], a1[3], b1[2], b1[3]);
        }
    }

    #pragma unroll
    for (int i = 0; i < 2; i++) {
        int r0 = brow + wm * 32 + i * 16 + g;
        #pragma unroll
        for (int j = 0; j < 4; j++) {
            int col = bcol + wn * 32 + j * 8 + 2 * t;
            float b0 = bias[col], b1 = bias[col + 1];
            float v00 = acc[i][j][0] + b0, v01 = acc[i][j][1] + b1;
            float v10 = acc[i][j][2] + b0, v11 = acc[i][j][3] + b1;
            if (ACT) { v00 = gelu_exact(v00); v01 = gelu_exact(v01);
                       v10 = gelu_exact(v10); v11 = gelu_exact(v11); }
            *(float2*)&Y[(size_t)r0 * Ndim + col]       = make_float2(v00, v01);
            *(float2*)&Y[(size_t)(r0 + 8) * Ndim + col] = make_float2(v10, v11);
        }
    }
}

// ---------------- flash attention, warp-owns-rows, ldmatrix + exp2 ----------------
// BQ=128 (8 warps x 16 rows), BKEY=64, DK=32. Softmax fully warp-local, base-2.
#define VST 40          // V smem stride (words): conflict-free scalar LDS (8t+g style)
#define PST 68          // P smem stride (words)
#define KSO 0
#define VSO (2 * 64 * KST)
#define PSO (VSO + 2 * 64 * VST)
#define ATTN_SMEM ((PSO + 128 * PST) * 4)
#define NKT (SS / 64)

__global__ __launch_bounds__(256)
void flash_attn_mma(const float* __restrict__ Q, const float* __restrict__ K,
                    const float* __restrict__ V, float* __restrict__ O) {
    extern __shared__ float sm[];
    const uint32_t sb = sptr(sm);
    float* Vsm = sm + VSO;
    float* Psm = sm + PSO;

    const int qt = blockIdx.x, h = blockIdx.y, b = blockIdx.z;
    const int tid = threadIdx.x, lane = tid & 31, w = tid >> 5;
    const int g = lane >> 2, t = lane & 3;
    const int m4 = lane >> 3, r8 = lane & 7;
    // 1/sqrt(32) * log2(e): softmax runs in base-2 domain
    const float scale2 = 0.17677669529663687f * 1.4426950408889634f;

    const float* Qb = Q + ((size_t)b * SS + (size_t)qt * 128) * DD + h * DKH;
    const float* Kb = K + (size_t)b * SS * DD + h * DKH;
    const float* Vb = V + (size_t)b * SS * DD + h * DKH;
    float*       Ob = O + ((size_t)b * SS + (size_t)qt * 128) * DD + h * DKH;

    // stage Q (128x32) into P region + prefetch K/V tile 0
    #pragma unroll
    for (int i = 0; i < 4; i++) {
        int idx = tid + 256 * i;
        int r = idx >> 3, c = (idx & 7) * 4;
        cp16(sb + (PSO + r * PST + c) * 4, &Qb[(size_t)r * DD + c]);
    }
    #pragma unroll
    for (int i = 0; i < 2; i++) {
        int idx = tid + 256 * i;
        int r = idx >> 3, c = (idx & 7) * 4;
        cp16(sb + (KSO + r * KST + c) * 4, &Kb[(size_t)r * DD + c]);
        cp16(sb + (VSO + r * VST + c) * 4, &Vb[(size_t)r * DD + c]);
    }
    cpcommit();
    cpwait<0>();
    __syncthreads();

    // per-lane ldmatrix offsets
    const int offQP = (w * 16 + (m4 & 1) * 8 + r8) * PST + (m4 >> 1) * 4;  // Q then P
    int offK[4];
    #pragma unroll
    for (int p = 0; p < 4; p++)
        offK[p] = ((p * 2 + (m4 >> 1)) * 8 + r8) * KST + (m4 & 1) * 4;

    // hoist Q fragments (scaled) into registers
    const int r0 = w * 16 + g, r1 = r0 + 8;
    uint32_t qa[4][4];
    #pragma unroll
    for (int ks = 0; ks < 4; ks++) {
        ldsm4(qa[ks], sb + (PSO + offQP + ks * 8) * 4);
        #pragma unroll
        for (int i = 0; i < 4; i++)
            qa[ks][i] = UF(__uint_as_float(qa[ks][i]) * scale2);
    }
    __syncthreads();   // Q reads done before P region is overwritten

    float m0 = -1e30f, m1 = -1e30f, l0 = 0.0f, l1 = 0.0f;
    float acc[4][4] = {};

    for (int kt = 0; kt < NKT; kt++) {
        cpwait<0>();
        __syncthreads();
        if (kt + 1 < NKT) {
            const float* Kn = Kb + (size_t)(kt + 1) * 64 * DD;
            const float* Vn = Vb + (size_t)(kt + 1) * 64 * DD;
            int kb_ = KSO + ((kt + 1) & 1) * 64 * KST;
            int vb_ = VSO + ((kt + 1) & 1) * 64 * VST;
            #pragma unroll
            for (int i = 0; i < 2; i++) {
                int idx = tid + 256 * i;
                int r = idx >> 3, c = (idx & 7) * 4;
                cp16(sb + (kb_ + r * KST + c) * 4, &Kn[(size_t)r * DD + c]);
                cp16(sb + (vb_ + r * VST + c) * 4, &Vn[(size_t)r * DD + c]);
            }
            cpcommit();
        }
        const int kbuf = KSO + (kt & 1) * 64 * KST;
        const float* Vc = Vsm + (kt & 1) * 64 * VST;

        // S = Q K^T (base-2 scaled): warp rows r0/r1, 64 keys
        float s[8][4] = {};
        #pragma unroll
        for (int ks = 0; ks < 4; ks++) {
            const int kk = ks * 8;
            uint32_t kb0[4], kb1[4], kb2[4], kb3[4];
            ldsm4(kb0, sb + (kbuf + offK[0] + kk) * 4);
            ldsm4(kb1, sb + (kbuf + offK[1] + kk) * 4);
            ldsm4(kb2, sb + (kbuf + offK[2] + kk) * 4);
            ldsm4(kb3, sb + (kbuf + offK[3] + kk) * 4);
            mma_tf32(s[0], qa[ks][0], qa[ks][1], qa[ks][2], qa[ks][3], kb0[0], kb0[1]);
            mma_tf32(s[1], qa[ks][0], qa[ks][1], qa[ks][2], qa[ks][3], kb0[2], kb0[3]);
            mma_tf32(s[2], qa[ks][0], qa[ks][1], qa[ks][2], qa[ks][3], kb1[0], kb1[1]);
            mma_tf32(s[3], qa[ks][0], qa[ks][1], qa[ks][2], qa[ks][3], kb1[2], kb1[3]);
            mma_tf32(s[4], qa[ks][0], qa[ks][1], qa[ks][2], qa[ks][3], kb2[0], kb2[1]);
            mma_tf32(s[5], qa[ks][0], qa[ks][1], qa[ks][2], qa[ks][3], kb2[2], kb2[3]);
            mma_tf32(s[6], qa[ks][0], qa[ks][1], qa[ks][2], qa[ks][3], kb3[0], kb3[1]);
            mma_tf32(s[7], qa[ks][0], qa[ks][1], qa[ks][2], qa[ks][3], kb3[2], kb3[3]);
        }

        // warp-local online softmax (base-2)
        float mx0 = -1e30f, mx1 = -1e30f;
        #pragma unroll
        for (int j = 0; j < 8; j++) {
            mx0 = fmaxf(mx0, fmaxf(s[j][0], s[j][1]));
            mx1 = fmaxf(mx1, fmaxf(s[j][2], s[j][3]));
        }
        mx0 = fmaxf(mx0, __shfl_xor_sync(0xffffffffu, mx0, 1));
        mx0 = fmaxf(mx0, __shfl_xor_sync(0xffffffffu, mx0, 2));
        mx1 = fmaxf(mx1, __shfl_xor_sync(0xffffffffu, mx1, 1));
        mx1 = fmaxf(mx1, __shfl_xor_sync(0xffffffffu, mx1, 2));
        float mn0 = fmaxf(m0, mx0), mn1 = fmaxf(m1, mx1);
        float al0 = ex2(m0 - mn0), al1 = ex2(m1 - mn1);
        m0 = mn0; m1 = mn1;

        float sum0 = 0.0f, sum1 = 0.0f;
        #pragma unroll
        for (int j = 0; j < 8; j++) {
            float p0 = ex2(s[j][0] - mn0), p1 = ex2(s[j][1] - mn0);
            float p2 = ex2(s[j][2] - mn1), p3 = ex2(s[j][3] - mn1);
            sum0 += p0 + p1; sum1 += p2 + p3;
            *(float2*)&Psm[r0 * PST + j * 8 + 2 * t] = make_float2(p0, p1);
            *(float2*)&Psm[r1 * PST + j * 8 + 2 * t] = make_float2(p2, p3);
        }
        sum0 += __shfl_xor_sync(0xffffffffu, sum0, 1);
        sum0 += __shfl_xor_sync(0xffffffffu, sum0, 2);
        sum1 += __shfl_xor_sync(0xffffffffu, sum1, 1);
        sum1 += __shfl_xor_sync(0xffffffffu, sum1, 2);
        l0 = l0 * al0 + sum0;
        l1 = l1 * al1 + sum1;

        #pragma unroll
        for (int j = 0; j < 4; j++) {
            acc[j][0] *= al0; acc[j][1] *= al0;
            acc[j][2] *= al1; acc[j][3] *= al1;
        }
        __syncwarp();   // P stores visible within warp

        // PV: O[r, d] += P[r, key] * V[key, d]
        #pragma unroll
        for (int ks = 0; ks < 8; ks++) {
            const int kk = ks * 8;
            uint32_t pa[4];
            ldsm4(pa, sb + (PSO + offQP + kk) * 4);
            #pragma unroll
            for (int j = 0; j < 4; j++) {
                int cb = j * 8 + g;
                mma_tf32(acc[j], pa[0], pa[1], pa[2], pa[3],
                         UF(Vc[(kk + t) * VST + cb]), UF(Vc[(kk + t + 4) * VST + cb]));
            }
        }
    }

    const float il0 = 1.0f / l0, il1 = 1.0f / l1;
    #pragma unroll
    for (int j = 0; j < 4; j++) {
        int col = j * 8 + 2 * t;
        *(float2*)&Ob[(size_t)r0 * DD + col] = make_float2(acc[j][0] * il0, acc[j][1] * il0);
        *(float2*)&Ob[(size_t)r1 * DD + col] = make_float2(acc[j][2] * il1, acc[j][3] * il1);
    }
}

// ---------------- fused residual + LayerNorm (warp per row, D=256, float4) ----------------
__global__ __launch_bounds__(256)
void ln_residual(const float* __restrict__ X, const float* __restrict__ R,
                 const float* __restrict__ g, const float* __restrict__ bta,
                 float* __restrict__ Y) {
    int row  = blockIdx.x * 8 + (threadIdx.x >> 5);
    int lane = threadIdx.x & 31;
    const float4* x4 = (const float4*)(X + (size_t)row * DD);
    const float4* r4 = (const float4*)(R + (size_t)row * DD);

    float4 v[2];
    float sum = 0.0f;
    #pragma unroll
    for (int k = 0; k < 2; k++) {
        float4 a = x4[lane + 32 * k], b = r4[lane + 32 * k];
        v[k] = make_float4(a.x + b.x, a.y + b.y, a.z + b.z, a.w + b.w);
        sum += v[k].x + v[k].y + v[k].z + v[k].w;
    }
    #pragma unroll
    for (int o = 16; o > 0; o >>= 1) sum += __shfl_xor_sync(0xffffffffu, sum, o);
    float mu = sum * (1.0f / 256.0f);

    float vs = 0.0f;
    #pragma unroll
    for (int k = 0; k < 2; k++) {
        float dx = v[k].x - mu, dy = v[k].y - mu, dz = v[k].z - mu, dw = v[k].w - mu;
        vs = fmaf(dx, dx, vs); vs = fmaf(dy, dy, vs);
        vs = fmaf(dz, dz, vs); vs = fmaf(dw, dw, vs);
    }
    #pragma unroll
    for (int o = 16; o > 0; o >>= 1) vs += __shfl_xor_sync(0xffffffffu, vs, o);
    float rstd = rsqrtf(vs * (1.0f / 256.0f) + 1e-5f);

    const float4* g4 = (const float4*)g;
    const float4* b4 = (const float4*)bta;
    float4* y4 = (float4*)(Y + (size_t)row * DD);
    #pragma unroll
    for (int k = 0; k < 2; k++) {
        float4 gg = g4[lane + 32 * k], bb = b4[lane + 32 * k];
        float4 o;
        o.x = (v[k].x - mu) * rstd * gg.x + bb.x;
        o.y = (v[k].y - mu) * rstd * gg.y + bb.y;
        o.z = (v[k].z - mu) * rstd * gg.z + bb.z;
        o.w = (v[k].w - mu) * rstd * gg.w + bb.w;
        y4[lane + 32 * k] = o;
    }
}

// ---------------- launch ----------------
extern "C" void kernel_launch(void* const* d_in, const int* in_sizes, int n_in,
                              void* d_out, int out_size) {
    const float* x       = (const float*)d_in[0];
    const float* Wq_down = (const float*)d_in[1];
    const float* bq_down = (const float*)d_in[2];
    const float* Wq_up   = (const float*)d_in[3];
    const float* bq_up   = (const float*)d_in[4];
    const float* Wk_down = (const float*)d_in[5];
    const float* bk_down = (const float*)d_in[6];
    const float* Wk_up   = (const float*)d_in[7];
    const float* bk_up   = (const float*)d_in[8];
    const float* Wv      = (const float*)d_in[9];
    const float* bv      = (const float*)d_in[10];
    const float* Wo      = (const float*)d_in[11];
    const float* bo      = (const float*)d_in[12];
    const float* ln_a_g  = (const float*)d_in[13];
    const float* ln_a_b  = (const float*)d_in[14];
    const float* W_ff1   = (const float*)d_in[15];
    const float* b_ff1   = (const float*)d_in[16];
    const float* W_ff2   = (const float*)d_in[17];
    const float* b_ff2   = (const float*)d_in[18];
    const float* ln_b_g  = (const float*)d_in[19];
    const float* ln_b_b  = (const float*)d_in[20];
    float* out = (float*)d_out;

    float *qd, *kd, *Qm, *Km, *Vm, *ctx, *ao, *ln1, *hb, *ff;
    cudaGetSymbolAddress((void**)&qd,  g_qd);
    cudaGetSymbolAddress((void**)&kd,  g_kd);
    cudaGetSymbolAddress((void**)&Qm,  g_Q);
    cudaGetSymbolAddress((void**)&Km,  g_K);
    cudaGetSymbolAddress((void**)&Vm,  g_V);
    cudaGetSymbolAddress((void**)&ctx, g_ctx);
    cudaGetSymbolAddress((void**)&ao,  g_ao);
    cudaGetSymbolAddress((void**)&ln1, g_ln1);
    cudaGetSymbolAddress((void**)&hb,  g_h);
    cudaGetSymbolAddress((void**)&ff,  g_ff);

    cudaFuncSetAttribute(gemm_tf32<0>, cudaFuncAttributeMaxDynamicSharedMemorySize, GEMM_SMEM);
    cudaFuncSetAttribute(gemm_tf32<1>, cudaFuncAttributeMaxDynamicSharedMemorySize, GEMM_SMEM);
    cudaFuncSetAttribute(flash_attn_mma, cudaFuncAttributeMaxDynamicSharedMemorySize, ATTN_SMEM);

    dim3 thr(256);
    // fused Q/K down-projections (N=64, K=256)
    gemm_tf32<0><<<dim3(1, MM / GBM, 2), thr, GEMM_SMEM>>>(
        x, Wq_down, bq_down, qd,  x, Wk_down, bk_down, kd, RH, DD);
    // fused Q/K up-projections (N=256, K=64)
    gemm_tf32<0><<<dim3(DD / GBN, MM / GBM, 2), thr, GEMM_SMEM>>>(
        qd, Wq_up, bq_up, Qm,  kd, Wk_up, bk_up, Km, DD, RH);
    // V projection
    gemm_tf32<0><<<dim3(DD / GBN, MM / GBM, 1), thr, GEMM_SMEM>>>(
        x, Wv, bv, Vm,  x, Wv, bv, Vm, DD, DD);
    // attention
    flash_attn_mma<<<dim3(SS / 128, HH, BB), thr, ATTN_SMEM>>>(Qm, Km, Vm, ctx);
    // output projection
    gemm_tf32<0><<<dim3(DD / GBN, MM / GBM, 1), thr, GEMM_SMEM>>>(
        ctx, Wo, bo, ao,  ctx, Wo, bo, ao, DD, DD);
    // LN(x + attn_out)
    ln_residual<<<MM / 8, thr>>>(x, ao, ln_a_g, ln_a_b, ln1);
    // FFN
    gemm_tf32<1><<<dim3(DFFC / GBN, MM / GBM, 1), thr, GEMM_SMEM>>>(
        ln1, W_ff1, b_ff1, hb,  ln1, W_ff1, b_ff1, hb, DFFC, DD);
    gemm_tf32<0><<<dim3(DD / GBN, MM / GBM, 1), thr, GEMM_SMEM>>>(
        hb, W_ff2, b_ff2, ff,  hb, W_ff2, b_ff2, ff, DD, DFFC);
    // final LN(ln1 + ff)
    ln_residual<<<MM / 8, thr>>>(ln1, ff, ln_b_g, ln_b_b, out);
}

// round 5
// speedup vs baseline: 7.9400x; 1.5432x over previous
#include <cuda_runtime.h>
#include <cuda_fp16.h>
#include <math.h>
#include <stdint.h>

// Problem constants
#define BB   4
#define SS   2048
#define DD   256
#define HH   8
#define DKH  32
#define RH   64          // RANK*H
#define DFFC 1024
#define MM   (BB*SS)     // 8192 rows

// ---------------- scratch (no allocs allowed) ----------------
// fp16 converted inputs/weights
__device__ __align__(16) __half g_x16 [MM*DD];
__device__ __align__(16) __half g_wqd16[RH*DD];
__device__ __align__(16) __half g_wkd16[RH*DD];
__device__ __align__(16) __half g_wqu16[DD*RH];
__device__ __align__(16) __half g_wku16[DD*RH];
__device__ __align__(16) __half g_wv16 [DD*DD];
__device__ __align__(16) __half g_wo16 [DD*DD];
__device__ __align__(16) __half g_wf116[DFFC*DD];
__device__ __align__(16) __half g_wf216[DD*DFFC];
// fp16 activations
__device__ __align__(16) __half g_qd16 [MM*RH];
__device__ __align__(16) __half g_kd16 [MM*RH];
__device__ __align__(16) __half g_Q16  [MM*DD];
__device__ __align__(16) __half g_K16  [MM*DD];
__device__ __align__(16) __half g_V16  [MM*DD];
__device__ __align__(16) __half g_ctx16[MM*DD];
__device__ __align__(16) __half g_ln116[MM*DD];
__device__ __align__(16) __half g_h16  [MM*DFFC];
// fp32 (feed LayerNorm residuals)
__device__ float g_ao [MM*DD];
__device__ float g_ln1[MM*DD];
__device__ float g_ff [MM*DD];

// ---------------- helpers ----------------
__device__ __forceinline__ uint32_t sptr(const void* p) {
    return (uint32_t)__cvta_generic_to_shared(p);
}
__device__ __forceinline__ void cp16(uint32_t s, const void* g) {
    asm volatile("cp.async.cg.shared.global [%0], [%1], 16;\n" :: "r"(s), "l"(g));
}
__device__ __forceinline__ void cpcommit() {
    asm volatile("cp.async.commit_group;\n" ::: "memory");
}
template<int N> __device__ __forceinline__ void cpwait() {
    asm volatile("cp.async.wait_group %0;\n" :: "n"(N) : "memory");
}
__device__ __forceinline__ void ldsm4(uint32_t* r, uint32_t addr) {
    asm volatile("ldmatrix.sync.aligned.m8n8.x4.shared.b16 {%0,%1,%2,%3}, [%4];"
                 : "=r"(r[0]), "=r"(r[1]), "=r"(r[2]), "=r"(r[3]) : "r"(addr));
}
__device__ __forceinline__ void ldsm4t(uint32_t* r, uint32_t addr) {
    asm volatile("ldmatrix.sync.aligned.m8n8.x4.trans.shared.b16 {%0,%1,%2,%3}, [%4];"
                 : "=r"(r[0]), "=r"(r[1]), "=r"(r[2]), "=r"(r[3]) : "r"(addr));
}
__device__ __forceinline__ void mma16(float* c, uint32_t a0, uint32_t a1,
                                      uint32_t a2, uint32_t a3,
                                      uint32_t b0, uint32_t b1) {
    asm volatile(
        "mma.sync.aligned.m16n8k16.row.col.f32.f16.f16.f32 "
        "{%0,%1,%2,%3},{%4,%5,%6,%7},{%8,%9},{%0,%1,%2,%3};"
        : "+f"(c[0]), "+f"(c[1]), "+f"(c[2]), "+f"(c[3])
        : "r"(a0), "r"(a1), "r"(a2), "r"(a3), "r"(b0), "r"(b1));
}
__device__ __forceinline__ float ex2(float x) {
    float r; asm("ex2.approx.f32 %0, %1;" : "=f"(r) : "f"(x)); return r;
}
__device__ __forceinline__ uint32_t packh2(float lo, float hi) {
    __half2 h = __floats2half2_rn(lo, hi);
    return *(uint32_t*)&h;
}
__device__ __forceinline__ float gelu_exact(float x) {
    return 0.5f * x * (1.0f + erff(x * 0.70710678118654752f));
}
__device__ __forceinline__ void st2(float* Y, size_t idx, float a, float b) {
    *(float2*)&Y[idx] = make_float2(a, b);
}
__device__ __forceinline__ void st2(__half* Y, size_t idx, float a, float b) {
    *(__half2*)&Y[idx] = __floats2half2_rn(a, b);
}

// ---------------- fp32 -> fp16 conversion (x + 8 weights, one launch) ----------------
#define F4_X   (MM*DD/4)      // 524288
#define F4_SM  (RH*DD/4)      // 4096
#define F4_WV  (DD*DD/4)      // 16384
#define F4_FF  (DFFC*DD/4)    // 65536
#define C0 F4_X
#define C1 (C0+F4_SM)
#define C2 (C1+F4_SM)
#define C3 (C2+F4_SM)
#define C4 (C3+F4_SM)
#define C5 (C4+F4_WV)
#define C6 (C5+F4_WV)
#define C7 (C6+F4_FF)
#define C8 (C7+F4_FF)

__device__ __forceinline__ void cvt4(__half* dst, const float* src, int i) {
    float4 v = ((const float4*)src)[i];
    uint2 u = make_uint2(packh2(v.x, v.y), packh2(v.z, v.w));
    *(uint2*)(dst + (size_t)i * 4) = u;
}

__global__ __launch_bounds__(256)
void convert_all(const float* x, const float* wqd, const float* wkd,
                 const float* wqu, const float* wku, const float* wv,
                 const float* wo, const float* wf1, const float* wf2) {
    for (int i = blockIdx.x * 256 + threadIdx.x; i < C8; i += gridDim.x * 256) {
        if      (i < C0) cvt4(g_x16,   x,   i);
        else if (i < C1) cvt4(g_wqd16, wqd, i - C0);
        else if (i < C2) cvt4(g_wkd16, wkd, i - C1);
        else if (i < C3) cvt4(g_wqu16, wqu, i - C2);
        else if (i < C4) cvt4(g_wku16, wku, i - C3);
        else if (i < C5) cvt4(g_wv16,  wv,  i - C4);
        else if (i < C6) cvt4(g_wo16,  wo,  i - C5);
        else if (i < C7) cvt4(g_wf116, wf1, i - C6);
        else             cvt4(g_wf216, wf2, i - C7);
    }
}

// ---------------- fp16 GEMM (dual): Y[M,N] = X[M,K] @ W[N,K]^T + b ----------------
// BM=128, BN=64, BK=64, 256 threads (8 warps, 4m x 2n), warp tile 32x32.
#define GBM 128
#define GBN 64
#define GBK 64
#define GST 72          // smem row stride (halves) = 144B: ldmatrix conflict-free
#define ABUF (GBM*GST)
#define BOFFH (2*ABUF)
#define BBUF (GBN*GST)
#define GEMM_SMEM ((BOFFH + 2*BBUF) * 2)

template<int ACT, typename TOUT>
__global__ __launch_bounds__(256)
void gemm_f16(const __half* __restrict__ X0, const __half* __restrict__ W0,
              const float* __restrict__ B0, TOUT* __restrict__ Y0,
              const __half* __restrict__ X1, const __half* __restrict__ W1,
              const float* __restrict__ B1, TOUT* __restrict__ Y1,
              int Ndim, int Kdim, float os0, float os1) {
    const __half* X   = blockIdx.z ? X1 : X0;
    const __half* W   = blockIdx.z ? W1 : W0;
    const float* bias = blockIdx.z ? B1 : B0;
    TOUT*        Y    = blockIdx.z ? Y1 : Y0;
    const float  os   = blockIdx.z ? os1 : os0;

    extern __shared__ __half smh[];
    const uint32_t sb = sptr(smh);

    const int tid  = threadIdx.x;
    const int lane = tid & 31, w = tid >> 5;
    const int wm = w >> 1, wn = w & 1;
    const int g = lane >> 2, t = lane & 3;
    const int brow = blockIdx.y * GBM;
    const int bcol = blockIdx.x * GBN;
    const int nk = Kdim / GBK;

    const int offA = (wm * 32 + (lane & 15)) * GST + (lane >> 4) * 8;
    const int offB = BOFFH + (wn * 32 + (lane & 7)) * GST + (lane >> 3) * 8;

    // prologue: tile 0 -> buf 0
    #pragma unroll
    for (int i = 0; i < 4; i++) {
        int idx = tid + 256 * i;
        int r = idx >> 3, c = (idx & 7) * 8;
        cp16(sb + (r * GST + c) * 2, &X[(size_t)(brow + r) * Kdim + c]);
    }
    #pragma unroll
    for (int i = 0; i < 2; i++) {
        int idx = tid + 256 * i;
        int r = idx >> 3, c = (idx & 7) * 8;
        cp16(sb + (BOFFH + r * GST + c) * 2, &W[(size_t)(bcol + r) * Kdim + c]);
    }
    cpcommit();

    float acc[2][4][4] = {};

    for (int k = 0; k < nk; k++) {
        cpwait<0>();
        __syncthreads();
        if (k + 1 < nk) {
            int k0 = (k + 1) * GBK;
            int ab = ((k + 1) & 1) * ABUF;
            int bb = ((k + 1) & 1) * BBUF;
            #pragma unroll
            for (int i = 0; i < 4; i++) {
                int idx = tid + 256 * i;
                int r = idx >> 3, c = (idx & 7) * 8;
                cp16(sb + (ab + r * GST + c) * 2, &X[(size_t)(brow + r) * Kdim + k0 + c]);
            }
            #pragma unroll
            for (int i = 0; i < 2; i++) {
                int idx = tid + 256 * i;
                int r = idx >> 3, c = (idx & 7) * 8;
                cp16(sb + (BOFFH + bb + r * GST + c) * 2, &W[(size_t)(bcol + r) * Kdim + k0 + c]);
            }
            cpcommit();
        }
        const int ab = (k & 1) * ABUF;
        const int bb = (k & 1) * BBUF;

        #pragma unroll
        for (int kg = 0; kg < 2; kg++) {
            uint32_t a[2][2][4];
            #pragma unroll
            for (int i = 0; i < 2; i++)
                #pragma unroll
                for (int ksl = 0; ksl < 2; ksl++)
                    ldsm4(a[i][ksl], sb + (ab + offA + i * 16 * GST + (kg * 2 + ksl) * 16) * 2);
            #pragma unroll
            for (int j = 0; j < 4; j++) {
                uint32_t b[4];
                ldsm4(b, sb + (bb + offB + j * 8 * GST + kg * 32) * 2);
                mma16(acc[0][j], a[0][0][0], a[0][0][1], a[0][0][2], a[0][0][3], b[0], b[1]);
                mma16(acc[1][j], a[1][0][0], a[1][0][1], a[1][0][2], a[1][0][3], b[0], b[1]);
                mma16(acc[0][j], a[0][1][0], a[0][1][1], a[0][1][2], a[0][1][3], b[2], b[3]);
                mma16(acc[1][j], a[1][1][0], a[1][1][1], a[1][1][2], a[1][1][3], b[2], b[3]);
            }
        }
    }

    #pragma unroll
    for (int i = 0; i < 2; i++) {
        int r0 = brow + wm * 32 + i * 16 + g;
        #pragma unroll
        for (int j = 0; j < 4; j++) {
            int col = bcol + wn * 32 + j * 8 + 2 * t;
            float b0 = bias[col], b1 = bias[col + 1];
            float v00 = acc[i][j][0] + b0, v01 = acc[i][j][1] + b1;
            float v10 = acc[i][j][2] + b0, v11 = acc[i][j][3] + b1;
            if (ACT) { v00 = gelu_exact(v00); v01 = gelu_exact(v01);
                       v10 = gelu_exact(v10); v11 = gelu_exact(v11); }
            st2(Y, (size_t)r0 * Ndim + col,       v00 * os, v01 * os);
            st2(Y, (size_t)(r0 + 8) * Ndim + col, v10 * os, v11 * os);
        }
    }
}

// ---------------- flash attention, fp16, register-resident P ----------------
// BQ=128 (8 warps x 16 rows), BKEY=64, DK=32. Q pre-scaled (softmax in base-2).
#define AKST 40         // K/V/Q smem stride (halves) = 80B
#define KSOH 0
#define VSOH (2*64*AKST)
#define QSOH (4*64*AKST)
#define NKT (SS / 64)

__global__ __launch_bounds__(256)
void flash_attn_f16(const __half* __restrict__ Q, const __half* __restrict__ K,
                    const __half* __restrict__ V, __half* __restrict__ O) {
    __shared__ __align__(16) __half smh[QSOH + 128 * AKST];
    const uint32_t sb = sptr(smh);

    const int qt = blockIdx.x, h = blockIdx.y, b = blockIdx.z;
    const int tid = threadIdx.x, lane = tid & 31, w = tid >> 5;
    const int g = lane >> 2, t = lane & 3;

    const __half* Qb = Q + ((size_t)b * SS + (size_t)qt * 128) * DD + h * DKH;
    const __half* Kb = K + (size_t)b * SS * DD + h * DKH;
    const __half* Vb = V + (size_t)b * SS * DD + h * DKH;
    __half*       Ob = O + ((size_t)b * SS + (size_t)qt * 128) * DD + h * DKH;

    // stage Q (128x32 halves) + prefetch K/V tile 0
    #pragma unroll
    for (int i = 0; i < 2; i++) {
        int idx = tid + 256 * i;
        int r = idx >> 2, c = (idx & 3) * 8;
        cp16(sb + (QSOH + r * AKST + c) * 2, &Qb[(size_t)r * DD + c]);
    }
    {
        int r = tid >> 2, c = (tid & 3) * 8;
        cp16(sb + (KSOH + r * AKST + c) * 2, &Kb[(size_t)r * DD + c]);
        cp16(sb + (VSOH + r * AKST + c) * 2, &Vb[(size_t)r * DD + c]);
    }
    cpcommit();
    cpwait<0>();
    __syncthreads();

    // per-lane ldmatrix offsets (halves)
    const int offQ = QSOH + (w * 16 + (lane & 15)) * AKST + (lane >> 4) * 8;
    const int offK = (lane & 7) * AKST + (lane >> 3) * 8;
    const int offV = (((lane >> 3) & 1) * 8 + (lane & 7)) * AKST + (lane >> 4) * 8;

    // Q fragments for the whole loop (Q already scaled by 1/sqrt(dk)*log2e)
    uint32_t qa[2][4];
    ldsm4(qa[0], sb + (offQ +  0) * 2);
    ldsm4(qa[1], sb + (offQ + 16) * 2);

    const int r0 = w * 16 + g, r1 = r0 + 8;
    float m0 = -1e30f, m1 = -1e30f, l0 = 0.0f, l1 = 0.0f;
    float acc[4][4] = {};

    for (int kt = 0; kt < NKT; kt++) {
        cpwait<0>();
        __syncthreads();
        if (kt + 1 < NKT) {
            const __half* Kn = Kb + (size_t)(kt + 1) * 64 * DD;
            const __half* Vn = Vb + (size_t)(kt + 1) * 64 * DD;
            int kbn = KSOH + ((kt + 1) & 1) * 64 * AKST;
            int vbn = VSOH + ((kt + 1) & 1) * 64 * AKST;
            int r = tid >> 2, c = (tid & 3) * 8;
            cp16(sb + (kbn + r * AKST + c) * 2, &Kn[(size_t)r * DD + c]);
            cp16(sb + (vbn + r * AKST + c) * 2, &Vn[(size_t)r * DD + c]);
            cpcommit();
        }
        const int kbuf = KSOH + (kt & 1) * 64 * AKST;
        const int vbuf = VSOH + (kt & 1) * 64 * AKST;

        // S = Q K^T : 8 n-tiles x 2 k-chunks
        float s[8][4] = {};
        #pragma unroll
        for (int j = 0; j < 8; j++) {
            uint32_t kb[4];
            ldsm4(kb, sb + (kbuf + offK + j * 8 * AKST) * 2);
            mma16(s[j], qa[0][0], qa[0][1], qa[0][2], qa[0][3], kb[0], kb[1]);
            mma16(s[j], qa[1][0], qa[1][1], qa[1][2], qa[1][3], kb[2], kb[3]);
        }

        // warp-local online softmax (base-2), P packed straight into A-frags
        float mx0 = -1e30f, mx1 = -1e30f;
        #pragma unroll
        for (int j = 0; j < 8; j++) {
            mx0 = fmaxf(mx0, fmaxf(s[j][0], s[j][1]));
            mx1 = fmaxf(mx1, fmaxf(s[j][2], s[j][3]));
        }
        mx0 = fmaxf(mx0, __shfl_xor_sync(0xffffffffu, mx0, 1));
        mx0 = fmaxf(mx0, __shfl_xor_sync(0xffffffffu, mx0, 2));
        mx1 = fmaxf(mx1, __shfl_xor_sync(0xffffffffu, mx1, 1));
        mx1 = fmaxf(mx1, __shfl_xor_sync(0xffffffffu, mx1, 2));
        float mn0 = fmaxf(m0, mx0), mn1 = fmaxf(m1, mx1);
        float al0 = ex2(m0 - mn0), al1 = ex2(m1 - mn1);
        m0 = mn0; m1 = mn1;

        uint32_t plo[8], phi[8];
        float sum0 = 0.0f, sum1 = 0.0f;
        #pragma unroll
        for (int j = 0; j < 8; j++) {
            float p0 = ex2(s[j][0] - mn0), p1 = ex2(s[j][1] - mn0);
            float p2 = ex2(s[j][2] - mn1), p3 = ex2(s[j][3] - mn1);
            sum0 += p0 + p1; sum1 += p2 + p3;
            plo[j] = packh2(p0, p1);
            phi[j] = packh2(p2, p3);
        }
        sum0 += __shfl_xor_sync(0xffffffffu, sum0, 1);
        sum0 += __shfl_xor_sync(0xffffffffu, sum0, 2);
        sum1 += __shfl_xor_sync(0xffffffffu, sum1, 1);
        sum1 += __shfl_xor_sync(0xffffffffu, sum1, 2);
        l0 = l0 * al0 + sum0;
        l1 = l1 * al1 + sum1;

        #pragma unroll
        for (int j = 0; j < 4; j++) {
            acc[j][0] *= al0; acc[j][1] *= al0;
            acc[j][2] *= al1; acc[j][3] *= al1;
        }

        // PV: O += P * V ; V B-frags via ldmatrix.trans, P from registers
        #pragma unroll
        for (int ks = 0; ks < 4; ks++) {
            uint32_t v0[4], v1[4];
            ldsm4t(v0, sb + (vbuf + offV + ks * 16 * AKST) * 2);
            ldsm4t(v1, sb + (vbuf + offV + ks * 16 * AKST + 16) * 2);
            uint32_t a0 = plo[2 * ks], a1 = phi[2 * ks];
            uint32_t a2 = plo[2 * ks + 1], a3 = phi[2 * ks + 1];
            mma16(acc[0], a0, a1, a2, a3, v0[0], v0[1]);
            mma16(acc[1], a0, a1, a2, a3, v0[2], v0[3]);
            mma16(acc[2], a0, a1, a2, a3, v1[0], v1[1]);
            mma16(acc[3], a0, a1, a2, a3, v1[2], v1[3]);
        }
    }

    const float il0 = 1.0f / l0, il1 = 1.0f / l1;
    #pragma unroll
    for (int j = 0; j < 4; j++) {
        int col = j * 8 + 2 * t;
        st2(Ob, (size_t)r0 * DD + col, acc[j][0] * il0, acc[j][1] * il0);
        st2(Ob, (size_t)r1 * DD + col, acc[j][2] * il1, acc[j][3] * il1);
    }
}

// ---------------- fused residual + LayerNorm (warp/row); optional fp16 copy ----------------
template<int W16>
__global__ __launch_bounds__(256)
void ln_residual(const float* __restrict__ X, const float* __restrict__ R,
                 const float* __restrict__ g, const float* __restrict__ bta,
                 float* __restrict__ Y, __half* __restrict__ Y16) {
    int row  = blockIdx.x * 8 + (threadIdx.x >> 5);
    int lane = threadIdx.x & 31;
    const float4* x4 = (const float4*)(X + (size_t)row * DD);
    const float4* r4 = (const float4*)(R + (size_t)row * DD);

    float4 v[2];
    float sum = 0.0f;
    #pragma unroll
    for (int k = 0; k < 2; k++) {
        float4 a = x4[lane + 32 * k], b = r4[lane + 32 * k];
        v[k] = make_float4(a.x + b.x, a.y + b.y, a.z + b.z, a.w + b.w);
        sum += v[k].x + v[k].y + v[k].z + v[k].w;
    }
    #pragma unroll
    for (int o = 16; o > 0; o >>= 1) sum += __shfl_xor_sync(0xffffffffu, sum, o);
    float mu = sum * (1.0f / 256.0f);

    float vs = 0.0f;
    #pragma unroll
    for (int k = 0; k < 2; k++) {
        float dx = v[k].x - mu, dy = v[k].y - mu, dz = v[k].z - mu, dw = v[k].w - mu;
        vs = fmaf(dx, dx, vs); vs = fmaf(dy, dy, vs);
        vs = fmaf(dz, dz, vs); vs = fmaf(dw, dw, vs);
    }
    #pragma unroll
    for (int o = 16; o > 0; o >>= 1) vs += __shfl_xor_sync(0xffffffffu, vs, o);
    float rstd = rsqrtf(vs * (1.0f / 256.0f) + 1e-5f);

    const float4* g4 = (const float4*)g;
    const float4* b4 = (const float4*)bta;
    float4* y4 = (float4*)(Y + (size_t)row * DD);
    #pragma unroll
    for (int k = 0; k < 2; k++) {
        float4 gg = g4[lane + 32 * k], bb = b4[lane + 32 * k];
        float4 o;
        o.x = (v[k].x - mu) * rstd * gg.x + bb.x;
        o.y = (v[k].y - mu) * rstd * gg.y + bb.y;
        o.z = (v[k].z - mu) * rstd * gg.z + bb.z;
        o.w = (v[k].w - mu) * rstd * gg.w + bb.w;
        y4[lane + 32 * k] = o;
        if (W16) {
            int col = (lane + 32 * k) * 4;
            uint2 u = make_uint2(packh2(o.x, o.y), packh2(o.z, o.w));
            *(uint2*)(Y16 + (size_t)row * DD + col) = u;
        }
    }
}

// ---------------- launch ----------------
extern "C" void kernel_launch(void* const* d_in, const int* in_sizes, int n_in,
                              void* d_out, int out_size) {
    const float* x       = (const float*)d_in[0];
    const float* Wq_down = (const float*)d_in[1];
    const float* bq_down = (const float*)d_in[2];
    const float* Wq_up   = (const float*)d_in[3];
    const float* bq_up   = (const float*)d_in[4];
    const float* Wk_down = (const float*)d_in[5];
    const float* bk_down = (const float*)d_in[6];
    const float* Wk_up   = (const float*)d_in[7];
    const float* bk_up   = (const float*)d_in[8];
    const float* Wv      = (const float*)d_in[9];
    const float* bv      = (const float*)d_in[10];
    const float* Wo      = (const float*)d_in[11];
    const float* bo      = (const float*)d_in[12];
    const float* ln_a_g  = (const float*)d_in[13];
    const float* ln_a_b  = (const float*)d_in[14];
    const float* W_ff1   = (const float*)d_in[15];
    const float* b_ff1   = (const float*)d_in[16];
    const float* W_ff2   = (const float*)d_in[17];
    const float* b_ff2   = (const float*)d_in[18];
    const float* ln_b_g  = (const float*)d_in[19];
    const float* ln_b_b  = (const float*)d_in[20];
    float* out = (float*)d_out;

    __half *x16, *wqd16, *wkd16, *wqu16, *wku16, *wv16, *wo16, *wf116, *wf216;
    __half *qd16, *kd16, *Q16, *K16, *V16, *ctx16, *ln116, *h16;
    float *ao, *ln1, *ff;
    cudaGetSymbolAddress((void**)&x16,   g_x16);
    cudaGetSymbolAddress((void**)&wqd16, g_wqd16);
    cudaGetSymbolAddress((void**)&wkd16, g_wkd16);
    cudaGetSymbolAddress((void**)&wqu16, g_wqu16);
    cudaGetSymbolAddress((void**)&wku16, g_wku16);
    cudaGetSymbolAddress((void**)&wv16,  g_wv16);
    cudaGetSymbolAddress((void**)&wo16,  g_wo16);
    cudaGetSymbolAddress((void**)&wf116, g_wf116);
    cudaGetSymbolAddress((void**)&wf216, g_wf216);
    cudaGetSymbolAddress((void**)&qd16,  g_qd16);
    cudaGetSymbolAddress((void**)&kd16,  g_kd16);
    cudaGetSymbolAddress((void**)&Q16,   g_Q16);
    cudaGetSymbolAddress((void**)&K16,   g_K16);
    cudaGetSymbolAddress((void**)&V16,   g_V16);
    cudaGetSymbolAddress((void**)&ctx16, g_ctx16);
    cudaGetSymbolAddress((void**)&ln116, g_ln116);
    cudaGetSymbolAddress((void**)&h16,   g_h16);
    cudaGetSymbolAddress((void**)&ao,    g_ao);
    cudaGetSymbolAddress((void**)&ln1,   g_ln1);
    cudaGetSymbolAddress((void**)&ff,    g_ff);

    cudaFuncSetAttribute(gemm_f16<0, __half>, cudaFuncAttributeMaxDynamicSharedMemorySize, GEMM_SMEM);
    cudaFuncSetAttribute(gemm_f16<0, float>,  cudaFuncAttributeMaxDynamicSharedMemorySize, GEMM_SMEM);
    cudaFuncSetAttribute(gemm_f16<1, __half>, cudaFuncAttributeMaxDynamicSharedMemorySize, GEMM_SMEM);

    const float scale2 = 0.17677669529663687f * 1.4426950408889634f;
    dim3 thr(256);

    convert_all<<<512, thr>>>(x, Wq_down, Wk_down, Wq_up, Wk_up, Wv, Wo, W_ff1, W_ff2);
    // fused Q/K down-projections (N=64, K=256)
    gemm_f16<0, __half><<<dim3(1, MM / GBM, 2), thr, GEMM_SMEM>>>(
        x16, wqd16, bq_down, qd16,  x16, wkd16, bk_down, kd16, RH, DD, 1.0f, 1.0f);
    // fused Q/K up-projections (N=256, K=64); Q pre-scaled for softmax
    gemm_f16<0, __half><<<dim3(DD / GBN, MM / GBM, 2), thr, GEMM_SMEM>>>(
        qd16, wqu16, bq_up, Q16,  kd16, wku16, bk_up, K16, DD, RH, scale2, 1.0f);
    // V projection
    gemm_f16<0, __half><<<dim3(DD / GBN, MM / GBM, 1), thr, GEMM_SMEM>>>(
        x16, wv16, bv, V16,  x16, wv16, bv, V16, DD, DD, 1.0f, 1.0f);
    // attention
    flash_attn_f16<<<dim3(SS / 128, HH, BB), thr>>>(Q16, K16, V16, ctx16);
    // output projection (fp32 out -> LN residual)
    gemm_f16<0, float><<<dim3(DD / GBN, MM / GBM, 1), thr, GEMM_SMEM>>>(
        ctx16, wo16, bo, ao,  ctx16, wo16, bo, ao, DD, DD, 1.0f, 1.0f);
    // LN(x + attn_out) -> fp32 + fp16
    ln_residual<1><<<MM / 8, thr>>>(x, ao, ln_a_g, ln_a_b, ln1, ln116);
    // FFN
    gemm_f16<1, __half><<<dim3(DFFC / GBN, MM / GBM, 1), thr, GEMM_SMEM>>>(
        ln116, wf116, b_ff1, h16,  ln116, wf116, b_ff1, h16, DFFC, DD, 1.0f, 1.0f);
    gemm_f16<0, float><<<dim3(DD / GBN, MM / GBM, 1), thr, GEMM_SMEM>>>(
        h16, wf216, b_ff2, ff,  h16, wf216, b_ff2, ff, DD, DFFC, 1.0f, 1.0f);
    // final LN
    ln_residual<0><<<MM / 8, thr>>>(ln1, ff, ln_b_g, ln_b_b, out, (__half*)nullptr);
}

// round 6
// speedup vs baseline: 8.7266x; 1.0991x over previous
#include <cuda_runtime.h>
#include <cuda_fp16.h>
#include <math.h>
#include <stdint.h>

// Problem constants
#define BB   4
#define SS   2048
#define DD   256
#define HH   8
#define DKH  32
#define RH   64          // RANK*H
#define DFFC 1024
#define MM   (BB*SS)     // 8192 rows

// ---------------- scratch (no allocs allowed) ----------------
__device__ __align__(16) __half g_x16 [MM*DD];
__device__ __align__(16) __half g_wqd16[RH*DD];
__device__ __align__(16) __half g_wkd16[RH*DD];
__device__ __align__(16) __half g_wqu16[DD*RH];
__device__ __align__(16) __half g_wku16[DD*RH];
__device__ __align__(16) __half g_wv16 [DD*DD];
__device__ __align__(16) __half g_wo16 [DD*DD];
__device__ __align__(16) __half g_wf116[DFFC*DD];
__device__ __align__(16) __half g_wf216[DD*DFFC];
__device__ __align__(16) __half g_qd16 [MM*RH];
__device__ __align__(16) __half g_kd16 [MM*RH];
__device__ __align__(16) __half g_Q16  [MM*DD];
__device__ __align__(16) __half g_K16  [MM*DD];
__device__ __align__(16) __half g_V16  [MM*DD];
__device__ __align__(16) __half g_ctx16[MM*DD];
__device__ __align__(16) __half g_ln116[MM*DD];
__device__ __align__(16) __half g_h16  [MM*DFFC];
__device__ float g_ao [MM*DD];
__device__ float g_ln1[MM*DD];
__device__ float g_ff [MM*DD];

// ---------------- helpers ----------------
__device__ __forceinline__ uint32_t sptr(const void* p) {
    return (uint32_t)__cvta_generic_to_shared(p);
}
__device__ __forceinline__ void cp16(uint32_t s, const void* g) {
    asm volatile("cp.async.cg.shared.global [%0], [%1], 16;\n" :: "r"(s), "l"(g));
}
__device__ __forceinline__ void cpcommit() {
    asm volatile("cp.async.commit_group;\n" ::: "memory");
}
template<int N> __device__ __forceinline__ void cpwait() {
    asm volatile("cp.async.wait_group %0;\n" :: "n"(N) : "memory");
}
__device__ __forceinline__ void ldsm4(uint32_t* r, uint32_t addr) {
    asm volatile("ldmatrix.sync.aligned.m8n8.x4.shared.b16 {%0,%1,%2,%3}, [%4];"
                 : "=r"(r[0]), "=r"(r[1]), "=r"(r[2]), "=r"(r[3]) : "r"(addr));
}
__device__ __forceinline__ void ldsm4t(uint32_t* r, uint32_t addr) {
    asm volatile("ldmatrix.sync.aligned.m8n8.x4.trans.shared.b16 {%0,%1,%2,%3}, [%4];"
                 : "=r"(r[0]), "=r"(r[1]), "=r"(r[2]), "=r"(r[3]) : "r"(addr));
}
__device__ __forceinline__ void mma16(float* c, uint32_t a0, uint32_t a1,
                                      uint32_t a2, uint32_t a3,
                                      uint32_t b0, uint32_t b1) {
    asm volatile(
        "mma.sync.aligned.m16n8k16.row.col.f32.f16.f16.f32 "
        "{%0,%1,%2,%3},{%4,%5,%6,%7},{%8,%9},{%0,%1,%2,%3};"
        : "+f"(c[0]), "+f"(c[1]), "+f"(c[2]), "+f"(c[3])
        : "r"(a0), "r"(a1), "r"(a2), "r"(a3), "r"(b0), "r"(b1));
}
__device__ __forceinline__ float ex2(float x) {
    float r; asm("ex2.approx.f32 %0, %1;" : "=f"(r) : "f"(x)); return r;
}
__device__ __forceinline__ uint32_t h2ex2(uint32_t x) {
    uint32_t r; asm("ex2.approx.f16x2 %0, %1;" : "=r"(r) : "r"(x)); return r;
}
__device__ __forceinline__ uint32_t packh2(float lo, float hi) {
    __half2 h = __floats2half2_rn(lo, hi);
    return *(uint32_t*)&h;
}
__device__ __forceinline__ float gelu_exact(float x) {
    return 0.5f * x * (1.0f + erff(x * 0.70710678118654752f));
}
__device__ __forceinline__ void st2(float* Y, size_t idx, float a, float b) {
    *(float2*)&Y[idx] = make_float2(a, b);
}
__device__ __forceinline__ void st2(__half* Y, size_t idx, float a, float b) {
    *(__half2*)&Y[idx] = __floats2half2_rn(a, b);
}

// ---------------- fp32 -> fp16 conversion ----------------
#define F4_X   (MM*DD/4)
#define F4_SM  (RH*DD/4)
#define F4_WV  (DD*DD/4)
#define F4_FF  (DFFC*DD/4)
#define C0 F4_X
#define C1 (C0+F4_SM)
#define C2 (C1+F4_SM)
#define C3 (C2+F4_SM)
#define C4 (C3+F4_SM)
#define C5 (C4+F4_WV)
#define C6 (C5+F4_WV)
#define C7 (C6+F4_FF)
#define C8 (C7+F4_FF)

__device__ __forceinline__ void cvt4(__half* dst, const float* src, int i) {
    float4 v = ((const float4*)src)[i];
    uint2 u = make_uint2(packh2(v.x, v.y), packh2(v.z, v.w));
    *(uint2*)(dst + (size_t)i * 4) = u;
}

__global__ __launch_bounds__(256)
void convert_all(const float* x, const float* wqd, const float* wkd,
                 const float* wqu, const float* wku, const float* wv,
                 const float* wo, const float* wf1, const float* wf2) {
    for (int i = blockIdx.x * 256 + threadIdx.x; i < C8; i += gridDim.x * 256) {
        if      (i < C0) cvt4(g_x16,   x,   i);
        else if (i < C1) cvt4(g_wqd16, wqd, i - C0);
        else if (i < C2) cvt4(g_wkd16, wkd, i - C1);
        else if (i < C3) cvt4(g_wqu16, wqu, i - C2);
        else if (i < C4) cvt4(g_wku16, wku, i - C3);
        else if (i < C5) cvt4(g_wv16,  wv,  i - C4);
        else if (i < C6) cvt4(g_wo16,  wo,  i - C5);
        else if (i < C7) cvt4(g_wf116, wf1, i - C6);
        else             cvt4(g_wf216, wf2, i - C7);
    }
}

// ---------------- fp16 GEMM (dual, STG-stage pipeline) ----------------
// BM=128, BN=64, BK=64, 256 threads (8 warps, 4m x 2n), warp tile 32x32.
#define GBM 128
#define GBN 64
#define GBK 64
#define GST 72
#define ABUF (GBM*GST)
#define BBUF (GBN*GST)
#define GSMEM(STG) ((STG) * (ABUF + BBUF) * 2)

template<int ACT, typename TOUT, int STG>
__global__ __launch_bounds__(256)
void gemm_f16(const __half* __restrict__ X0, const __half* __restrict__ W0,
              const float* __restrict__ B0, TOUT* __restrict__ Y0,
              const __half* __restrict__ X1, const __half* __restrict__ W1,
              const float* __restrict__ B1, TOUT* __restrict__ Y1,
              int Ndim, int Kdim, float os0, float os1) {
    const __half* X   = blockIdx.z ? X1 : X0;
    const __half* W   = blockIdx.z ? W1 : W0;
    const float* bias = blockIdx.z ? B1 : B0;
    TOUT*        Y    = blockIdx.z ? Y1 : Y0;
    const float  os   = blockIdx.z ? os1 : os0;

    extern __shared__ __half smh[];
    const uint32_t sb = sptr(smh);
    const int BOFFH = STG * ABUF;

    const int tid  = threadIdx.x;
    const int lane = tid & 31, w = tid >> 5;
    const int wm = w >> 1, wn = w & 1;
    const int g = lane >> 2, t = lane & 3;
    const int brow = blockIdx.y * GBM;
    const int bcol = blockIdx.x * GBN;
    const int nk = Kdim / GBK;

    const int offA = (wm * 32 + (lane & 15)) * GST + (lane >> 4) * 8;
    const int offB = (wn * 32 + (lane & 7)) * GST + (lane >> 3) * 8;

    const int lr = tid >> 3, lc = (tid & 7) * 8;

    // prologue: issue first STG-1 tiles, one commit group each
    #pragma unroll
    for (int st = 0; st < STG - 1; st++) {
        if (st < nk) {
            int k0 = st * GBK;
            #pragma unroll
            for (int i = 0; i < 4; i++) {
                int r = lr + 32 * i;
                cp16(sb + (st * ABUF + r * GST + lc) * 2, &X[(size_t)(brow + r) * Kdim + k0 + lc]);
            }
            #pragma unroll
            for (int i = 0; i < 2; i++) {
                int r = lr + 32 * i;
                cp16(sb + (BOFFH + st * BBUF + r * GST + lc) * 2, &W[(size_t)(bcol + r) * Kdim + k0 + lc]);
            }
        }
        cpcommit();
    }

    float acc[2][4][4] = {};

    for (int k = 0; k < nk; k++) {
        cpwait<STG - 2>();
        __syncthreads();
        {
            int kp = k + STG - 1;
            if (kp < nk) {
                int k0 = kp * GBK;
                int st = kp % STG;
                #pragma unroll
                for (int i = 0; i < 4; i++) {
                    int r = lr + 32 * i;
                    cp16(sb + (st * ABUF + r * GST + lc) * 2, &X[(size_t)(brow + r) * Kdim + k0 + lc]);
                }
                #pragma unroll
                for (int i = 0; i < 2; i++) {
                    int r = lr + 32 * i;
                    cp16(sb + (BOFFH + st * BBUF + r * GST + lc) * 2, &W[(size_t)(bcol + r) * Kdim + k0 + lc]);
                }
            }
            cpcommit();
        }
        const int ab = (k % STG) * ABUF;
        const int bb = BOFFH + (k % STG) * BBUF;

        #pragma unroll
        for (int kg = 0; kg < 2; kg++) {
            uint32_t a[2][2][4];
            #pragma unroll
            for (int i = 0; i < 2; i++)
                #pragma unroll
                for (int ksl = 0; ksl < 2; ksl++)
                    ldsm4(a[i][ksl], sb + (ab + offA + i * 16 * GST + (kg * 2 + ksl) * 16) * 2);
            #pragma unroll
            for (int j = 0; j < 4; j++) {
                uint32_t b[4];
                ldsm4(b, sb + (bb + offB + j * 8 * GST + kg * 32) * 2);
                mma16(acc[0][j], a[0][0][0], a[0][0][1], a[0][0][2], a[0][0][3], b[0], b[1]);
                mma16(acc[1][j], a[1][0][0], a[1][0][1], a[1][0][2], a[1][0][3], b[0], b[1]);
                mma16(acc[0][j], a[0][1][0], a[0][1][1], a[0][1][2], a[0][1][3], b[2], b[3]);
                mma16(acc[1][j], a[1][1][0], a[1][1][1], a[1][1][2], a[1][1][3], b[2], b[3]);
            }
        }
    }

    #pragma unroll
    for (int i = 0; i < 2; i++) {
        int r0 = brow + wm * 32 + i * 16 + g;
        #pragma unroll
        for (int j = 0; j < 4; j++) {
            int col = bcol + wn * 32 + j * 8 + 2 * t;
            float b0 = bias[col], b1 = bias[col + 1];
            float v00 = acc[i][j][0] + b0, v01 = acc[i][j][1] + b1;
            float v10 = acc[i][j][2] + b0, v11 = acc[i][j][3] + b1;
            if (ACT) { v00 = gelu_exact(v00); v01 = gelu_exact(v01);
                       v10 = gelu_exact(v10); v11 = gelu_exact(v11); }
            st2(Y, (size_t)r0 * Ndim + col,       v00 * os, v01 * os);
            st2(Y, (size_t)(r0 + 8) * Ndim + col, v10 * os, v11 * os);
        }
    }
}

// ---------------- flash attention: fp16, f16x2 softmax, l via MMA, 3-stage ----------------
#define AKST 40
#define AST (64*AKST)
#define QOFF (6*AST)
#define NKT (SS / 64)
#define ONE2 0x3C003C00u

__global__ __launch_bounds__(256)
void flash_attn_f16(const __half* __restrict__ Q, const __half* __restrict__ K,
                    const __half* __restrict__ V, __half* __restrict__ O) {
    __shared__ __align__(16) __half smh[QOFF + 128 * AKST];
    const uint32_t sb = sptr(smh);

    const int qt = blockIdx.x, h = blockIdx.y, b = blockIdx.z;
    const int tid = threadIdx.x, lane = tid & 31, w = tid >> 5;
    const int g = lane >> 2, t = lane & 3;

    const __half* Qb = Q + ((size_t)b * SS + (size_t)qt * 128) * DD + h * DKH;
    const __half* Kb = K + (size_t)b * SS * DD + h * DKH;
    const __half* Vb = V + (size_t)b * SS * DD + h * DKH;
    __half*       Ob = O + ((size_t)b * SS + (size_t)qt * 128) * DD + h * DKH;

    const int lr = tid >> 2, lc = (tid & 3) * 8;

    // prologue: G0 = Q + K/V tile 0; G1 = K/V tile 1
    #pragma unroll
    for (int i = 0; i < 2; i++) {
        int r = lr + 64 * i;
        cp16(sb + (QOFF + r * AKST + lc) * 2, &Qb[(size_t)r * DD + lc]);
    }
    cp16(sb + (lr * AKST + lc) * 2, &Kb[(size_t)lr * DD + lc]);
    cp16(sb + (3 * AST + lr * AKST + lc) * 2, &Vb[(size_t)lr * DD + lc]);
    cpcommit();
    cp16(sb + (AST + lr * AKST + lc) * 2, &Kb[(size_t)(64 + lr) * DD + lc]);
    cp16(sb + (4 * AST + lr * AKST + lc) * 2, &Vb[(size_t)(64 + lr) * DD + lc]);
    cpcommit();

    cpwait<1>();
    __syncthreads();

    // per-lane ldmatrix offsets (halves)
    const int offQ = QOFF + (w * 16 + (lane & 15)) * AKST + (lane >> 4) * 8;
    const int offK = (lane & 7) * AKST + (lane >> 3) * 8;
    const int offV = (((lane >> 3) & 1) * 8 + (lane & 7)) * AKST + (lane >> 4) * 8;

    // Q fragments (Q pre-scaled by 1/sqrt(dk)*log2e in projection epilogue)
    uint32_t qa[2][4];
    ldsm4(qa[0], sb + (offQ +  0) * 2);
    ldsm4(qa[1], sb + (offQ + 16) * 2);

    const int r0 = w * 16 + g, r1 = r0 + 8;
    float m0 = -1e30f, m1 = -1e30f;
    float acc[4][4] = {};
    float accL[4] = {};   // row-sum accumulator via P @ ones

    for (int kt = 0; kt < NKT; kt++) {
        cpwait<1>();
        __syncthreads();
        {
            int kp = kt + 2;
            if (kp < NKT) {
                int st = kp % 3;
                const __half* Kn = Kb + (size_t)kp * 64 * DD;
                const __half* Vn = Vb + (size_t)kp * 64 * DD;
                cp16(sb + (st * AST + lr * AKST + lc) * 2, &Kn[(size_t)lr * DD + lc]);
                cp16(sb + ((3 + st) * AST + lr * AKST + lc) * 2, &Vn[(size_t)lr * DD + lc]);
            }
            cpcommit();
        }
        const int kbuf = (kt % 3) * AST;
        const int vbuf = (3 + kt % 3) * AST;

        // S = Q K^T
        float s[8][4] = {};
        #pragma unroll
        for (int j = 0; j < 8; j++) {
            uint32_t kb[4];
            ldsm4(kb, sb + (kbuf + offK + j * 8 * AKST) * 2);
            mma16(s[j], qa[0][0], qa[0][1], qa[0][2], qa[0][3], kb[0], kb[1]);
            mma16(s[j], qa[1][0], qa[1][1], qa[1][2], qa[1][3], kb[2], kb[3]);
        }

        // warp-local max (base-2 domain)
        float mx0 = -1e30f, mx1 = -1e30f;
        #pragma unroll
        for (int j = 0; j < 8; j++) {
            mx0 = fmaxf(mx0, fmaxf(s[j][0], s[j][1]));
            mx1 = fmaxf(mx1, fmaxf(s[j][2], s[j][3]));
        }
        mx0 = fmaxf(mx0, __shfl_xor_sync(0xffffffffu, mx0, 1));
        mx0 = fmaxf(mx0, __shfl_xor_sync(0xffffffffu, mx0, 2));
        mx1 = fmaxf(mx1, __shfl_xor_sync(0xffffffffu, mx1, 1));
        mx1 = fmaxf(mx1, __shfl_xor_sync(0xffffffffu, mx1, 2));
        float mn0 = fmaxf(m0, mx0), mn1 = fmaxf(m1, mx1);
        float al0 = ex2(m0 - mn0), al1 = ex2(m1 - mn1);
        m0 = mn0; m1 = mn1;

        // p = 2^(s - mn) computed in f16x2 — result IS the packed A-fragment
        const __half2 mn0h = __float2half2_rn(mn0);
        const __half2 mn1h = __float2half2_rn(mn1);
        uint32_t plo[8], phi[8];
        #pragma unroll
        for (int j = 0; j < 8; j++) {
            __half2 a = __hsub2(__floats2half2_rn(s[j][0], s[j][1]), mn0h);
            __half2 c = __hsub2(__floats2half2_rn(s[j][2], s[j][3]), mn1h);
            plo[j] = h2ex2(*(uint32_t*)&a);
            phi[j] = h2ex2(*(uint32_t*)&c);
        }

        // rescale accumulators
        #pragma unroll
        for (int j = 0; j < 4; j++) {
            acc[j][0] *= al0; acc[j][1] *= al0;
            acc[j][2] *= al1; acc[j][3] *= al1;
        }
        accL[0] *= al0; accL[2] *= al1;

        // PV + row-sum: O += P*V, accL += P*ones
        #pragma unroll
        for (int ks = 0; ks < 4; ks++) {
            uint32_t v0[4], v1[4];
            ldsm4t(v0, sb + (vbuf + offV + ks * 16 * AKST) * 2);
            ldsm4t(v1, sb + (vbuf + offV + ks * 16 * AKST + 16) * 2);
            uint32_t a0 = plo[2 * ks], a1 = phi[2 * ks];
            uint32_t a2 = plo[2 * ks + 1], a3 = phi[2 * ks + 1];
            mma16(acc[0], a0, a1, a2, a3, v0[0], v0[1]);
            mma16(acc[1], a0, a1, a2, a3, v0[2], v0[3]);
            mma16(acc[2], a0, a1, a2, a3, v1[0], v1[1]);
            mma16(acc[3], a0, a1, a2, a3, v1[2], v1[3]);
            mma16(accL, a0, a1, a2, a3, ONE2, ONE2);
        }
    }

    const float il0 = 1.0f / accL[0], il1 = 1.0f / accL[2];
    #pragma unroll
    for (int j = 0; j < 4; j++) {
        int col = j * 8 + 2 * t;
        st2(Ob, (size_t)r0 * DD + col, acc[j][0] * il0, acc[j][1] * il0);
        st2(Ob, (size_t)r1 * DD + col, acc[j][2] * il1, acc[j][3] * il1);
    }
}

// ---------------- fused residual + LayerNorm ----------------
template<int W16>
__global__ __launch_bounds__(256)
void ln_residual(const float* __restrict__ X, const float* __restrict__ R,
                 const float* __restrict__ g, const float* __restrict__ bta,
                 float* __restrict__ Y, __half* __restrict__ Y16) {
    int row  = blockIdx.x * 8 + (threadIdx.x >> 5);
    int lane = threadIdx.x & 31;
    const float4* x4 = (const float4*)(X + (size_t)row * DD);
    const float4* r4 = (const float4*)(R + (size_t)row * DD);

    float4 v[2];
    float sum = 0.0f;
    #pragma unroll
    for (int k = 0; k < 2; k++) {
        float4 a = x4[lane + 32 * k], b = r4[lane + 32 * k];
        v[k] = make_float4(a.x + b.x, a.y + b.y, a.z + b.z, a.w + b.w);
        sum += v[k].x + v[k].y + v[k].z + v[k].w;
    }
    #pragma unroll
    for (int o = 16; o > 0; o >>= 1) sum += __shfl_xor_sync(0xffffffffu, sum, o);
    float mu = sum * (1.0f / 256.0f);

    float vs = 0.0f;
    #pragma unroll
    for (int k = 0; k < 2; k++) {
        float dx = v[k].x - mu, dy = v[k].y - mu, dz = v[k].z - mu, dw = v[k].w - mu;
        vs = fmaf(dx, dx, vs); vs = fmaf(dy, dy, vs);
        vs = fmaf(dz, dz, vs); vs = fmaf(dw, dw, vs);
    }
    #pragma unroll
    for (int o = 16; o > 0; o >>= 1) vs += __shfl_xor_sync(0xffffffffu, vs, o);
    float rstd = rsqrtf(vs * (1.0f / 256.0f) + 1e-5f);

    const float4* g4 = (const float4*)g;
    const float4* b4 = (const float4*)bta;
    float4* y4 = (float4*)(Y + (size_t)row * DD);
    #pragma unroll
    for (int k = 0; k < 2; k++) {
        float4 gg = g4[lane + 32 * k], bb = b4[lane + 32 * k];
        float4 o;
        o.x = (v[k].x - mu) * rstd * gg.x + bb.x;
        o.y = (v[k].y - mu) * rstd * gg.y + bb.y;
        o.z = (v[k].z - mu) * rstd * gg.z + bb.z;
        o.w = (v[k].w - mu) * rstd * gg.w + bb.w;
        y4[lane + 32 * k] = o;
        if (W16) {
            int col = (lane + 32 * k) * 4;
            uint2 u = make_uint2(packh2(o.x, o.y), packh2(o.z, o.w));
            *(uint2*)(Y16 + (size_t)row * DD + col) = u;
        }
    }
}

// ---------------- launch ----------------
extern "C" void kernel_launch(void* const* d_in, const int* in_sizes, int n_in,
                              void* d_out, int out_size) {
    const float* x       = (const float*)d_in[0];
    const float* Wq_down = (const float*)d_in[1];
    const float* bq_down = (const float*)d_in[2];
    const float* Wq_up   = (const float*)d_in[3];
    const float* bq_up   = (const float*)d_in[4];
    const float* Wk_down = (const float*)d_in[5];
    const float* bk_down = (const float*)d_in[6];
    const float* Wk_up   = (const float*)d_in[7];
    const float* bk_up   = (const float*)d_in[8];
    const float* Wv      = (const float*)d_in[9];
    const float* bv      = (const float*)d_in[10];
    const float* Wo      = (const float*)d_in[11];
    const float* bo      = (const float*)d_in[12];
    const float* ln_a_g  = (const float*)d_in[13];
    const float* ln_a_b  = (const float*)d_in[14];
    const float* W_ff1   = (const float*)d_in[15];
    const float* b_ff1   = (const float*)d_in[16];
    const float* W_ff2   = (const float*)d_in[17];
    const float* b_ff2   = (const float*)d_in[18];
    const float* ln_b_g  = (const float*)d_in[19];
    const float* ln_b_b  = (const float*)d_in[20];
    float* out = (float*)d_out;

    __half *x16, *wqd16, *wkd16, *wqu16, *wku16, *wv16, *wo16, *wf116, *wf216;
    __half *qd16, *kd16, *Q16, *K16, *V16, *ctx16, *ln116, *h16;
    float *ao, *ln1, *ff;
    cudaGetSymbolAddress((void**)&x16,   g_x16);
    cudaGetSymbolAddress((void**)&wqd16, g_wqd16);
    cudaGetSymbolAddress((void**)&wkd16, g_wkd16);
    cudaGetSymbolAddress((void**)&wqu16, g_wqu16);
    cudaGetSymbolAddress((void**)&wku16, g_wku16);
    cudaGetSymbolAddress((void**)&wv16,  g_wv16);
    cudaGetSymbolAddress((void**)&wo16,  g_wo16);
    cudaGetSymbolAddress((void**)&wf116, g_wf116);
    cudaGetSymbolAddress((void**)&wf216, g_wf216);
    cudaGetSymbolAddress((void**)&qd16,  g_qd16);
    cudaGetSymbolAddress((void**)&kd16,  g_kd16);
    cudaGetSymbolAddress((void**)&Q16,   g_Q16);
    cudaGetSymbolAddress((void**)&K16,   g_K16);
    cudaGetSymbolAddress((void**)&V16,   g_V16);
    cudaGetSymbolAddress((void**)&ctx16, g_ctx16);
    cudaGetSymbolAddress((void**)&ln116, g_ln116);
    cudaGetSymbolAddress((void**)&h16,   g_h16);
    cudaGetSymbolAddress((void**)&ao,    g_ao);
    cudaGetSymbolAddress((void**)&ln1,   g_ln1);
    cudaGetSymbolAddress((void**)&ff,    g_ff);

    cudaFuncSetAttribute(gemm_f16<0, __half, 3>, cudaFuncAttributeMaxDynamicSharedMemorySize, GSMEM(3));
    cudaFuncSetAttribute(gemm_f16<0, __half, 2>, cudaFuncAttributeMaxDynamicSharedMemorySize, GSMEM(2));
    cudaFuncSetAttribute(gemm_f16<0, float, 3>,  cudaFuncAttributeMaxDynamicSharedMemorySize, GSMEM(3));
    cudaFuncSetAttribute(gemm_f16<1, __half, 3>, cudaFuncAttributeMaxDynamicSharedMemorySize, GSMEM(3));

    const float scale2 = 0.17677669529663687f * 1.4426950408889634f;
    dim3 thr(256);

    convert_all<<<512, thr>>>(x, Wq_down, Wk_down, Wq_up, Wk_up, Wv, Wo, W_ff1, W_ff2);
    // fused Q/K down-projections (N=64, K=256, nk=4)
    gemm_f16<0, __half, 3><<<dim3(1, MM / GBM, 2), thr, GSMEM(3)>>>(
        x16, wqd16, bq_down, qd16,  x16, wkd16, bk_down, kd16, RH, DD, 1.0f, 1.0f);
    // fused Q/K up-projections (N=256, K=64, nk=1); Q pre-scaled for softmax
    gemm_f16<0, __half, 2><<<dim3(DD / GBN, MM / GBM, 2), thr, GSMEM(2)>>>(
        qd16, wqu16, bq_up, Q16,  kd16, wku16, bk_up, K16, DD, RH, scale2, 1.0f);
    // V projection (nk=4)
    gemm_f16<0, __half, 3><<<dim3(DD / GBN, MM / GBM, 1), thr, GSMEM(3)>>>(
        x16, wv16, bv, V16,  x16, wv16, bv, V16, DD, DD, 1.0f, 1.0f);
    // attention
    flash_attn_f16<<<dim3(SS / 128, HH, BB), thr>>>(Q16, K16, V16, ctx16);
    // output projection (fp32 out -> LN residual)
    gemm_f16<0, float, 3><<<dim3(DD / GBN, MM / GBM, 1), thr, GSMEM(3)>>>(
        ctx16, wo16, bo, ao,  ctx16, wo16, bo, ao, DD, DD, 1.0f, 1.0f);
    // LN(x + attn_out) -> fp32 + fp16
    ln_residual<1><<<MM / 8, thr>>>(x, ao, ln_a_g, ln_a_b, ln1, ln116);
    // FFN
    gemm_f16<1, __half, 3><<<dim3(DFFC / GBN, MM / GBM, 1), thr, GSMEM(3)>>>(
        ln116, wf116, b_ff1, h16,  ln116, wf116, b_ff1, h16, DFFC, DD, 1.0f, 1.0f);
    gemm_f16<0, float, 3><<<dim3(DD / GBN, MM / GBM, 1), thr, GSMEM(3)>>>(
        h16, wf216, b_ff2, ff,  h16, wf216, b_ff2, ff, DD, DFFC, 1.0f, 1.0f);
    // final LN
    ln_residual<0><<<MM / 8, thr>>>(ln1, ff, ln_b_g, ln_b_b, out, (__half*)nullptr);
}

// round 7
// speedup vs baseline: 9.1849x; 1.0525x over previous
#include <cuda_runtime.h>
#include <cuda_fp16.h>
#include <math.h>
#include <stdint.h>

// Problem constants
#define BB   4
#define SS   2048
#define DD   256
#define HH   8
#define DKH  32
#define RH   64          // RANK*H
#define DFFC 1024
#define MM   (BB*SS)     // 8192 rows

// ---------------- scratch (no allocs allowed) ----------------
__device__ __align__(16) __half g_x16 [MM*DD];
__device__ __align__(16) __half g_wqd16[RH*DD];
__device__ __align__(16) __half g_wkd16[RH*DD];
__device__ __align__(16) __half g_wqu16[DD*RH];
__device__ __align__(16) __half g_wku16[DD*RH];
__device__ __align__(16) __half g_wv16 [DD*DD];
__device__ __align__(16) __half g_wo16 [DD*DD];
__device__ __align__(16) __half g_wf116[DFFC*DD];
__device__ __align__(16) __half g_wf216[DD*DFFC];
__device__ __align__(16) __half g_qd16 [MM*RH];
__device__ __align__(16) __half g_kd16 [MM*RH];
__device__ __align__(16) __half g_Q16  [MM*DD];
__device__ __align__(16) __half g_K16  [MM*DD];
__device__ __align__(16) __half g_V16  [MM*DD];
__device__ __align__(16) __half g_ctx16[MM*DD];
__device__ __align__(16) __half g_ln116[MM*DD];
__device__ __align__(16) __half g_h16  [MM*DFFC];
__device__ float g_ao [MM*DD];
__device__ float g_ln1[MM*DD];
__device__ float g_ff [MM*DD];

// ---------------- helpers ----------------
__device__ __forceinline__ uint32_t sptr(const void* p) {
    return (uint32_t)__cvta_generic_to_shared(p);
}
__device__ __forceinline__ void cp16(uint32_t s, const void* g) {
    asm volatile("cp.async.cg.shared.global [%0], [%1], 16;\n" :: "r"(s), "l"(g));
}
__device__ __forceinline__ void cpcommit() {
    asm volatile("cp.async.commit_group;\n" ::: "memory");
}
template<int N> __device__ __forceinline__ void cpwait() {
    asm volatile("cp.async.wait_group %0;\n" :: "n"(N) : "memory");
}
__device__ __forceinline__ void ldsm4(uint32_t* r, uint32_t addr) {
    asm volatile("ldmatrix.sync.aligned.m8n8.x4.shared.b16 {%0,%1,%2,%3}, [%4];"
                 : "=r"(r[0]), "=r"(r[1]), "=r"(r[2]), "=r"(r[3]) : "r"(addr));
}
__device__ __forceinline__ void ldsm4t(uint32_t* r, uint32_t addr) {
    asm volatile("ldmatrix.sync.aligned.m8n8.x4.trans.shared.b16 {%0,%1,%2,%3}, [%4];"
                 : "=r"(r[0]), "=r"(r[1]), "=r"(r[2]), "=r"(r[3]) : "r"(addr));
}
__device__ __forceinline__ void mma16(float* c, uint32_t a0, uint32_t a1,
                                      uint32_t a2, uint32_t a3,
                                      uint32_t b0, uint32_t b1) {
    asm volatile(
        "mma.sync.aligned.m16n8k16.row.col.f32.f16.f16.f32 "
        "{%0,%1,%2,%3},{%4,%5,%6,%7},{%8,%9},{%0,%1,%2,%3};"
        : "+f"(c[0]), "+f"(c[1]), "+f"(c[2]), "+f"(c[3])
        : "r"(a0), "r"(a1), "r"(a2), "r"(a3), "r"(b0), "r"(b1));
}
__device__ __forceinline__ float ex2(float x) {
    float r; asm("ex2.approx.f32 %0, %1;" : "=f"(r) : "f"(x)); return r;
}
__device__ __forceinline__ uint32_t h2ex2(uint32_t x) {
    uint32_t r; asm("ex2.approx.f16x2 %0, %1;" : "=r"(r) : "r"(x)); return r;
}
__device__ __forceinline__ uint32_t packh2(float lo, float hi) {
    __half2 h = __floats2half2_rn(lo, hi);
    return *(uint32_t*)&h;
}
__device__ __forceinline__ float gelu_exact(float x) {
    return 0.5f * x * (1.0f + erff(x * 0.70710678118654752f));
}
__device__ __forceinline__ void st2(float* Y, size_t idx, float a, float b) {
    *(float2*)&Y[idx] = make_float2(a, b);
}
__device__ __forceinline__ void st2(__half* Y, size_t idx, float a, float b) {
    *(__half2*)&Y[idx] = __floats2half2_rn(a, b);
}

// ---------------- fp32 -> fp16 conversion ----------------
#define F4_X   (MM*DD/4)
#define F4_SM  (RH*DD/4)
#define F4_WV  (DD*DD/4)
#define F4_FF  (DFFC*DD/4)
#define C0 F4_X
#define C1 (C0+F4_SM)
#define C2 (C1+F4_SM)
#define C3 (C2+F4_SM)
#define C4 (C3+F4_SM)
#define C5 (C4+F4_WV)
#define C6 (C5+F4_WV)
#define C7 (C6+F4_FF)
#define C8 (C7+F4_FF)

__device__ __forceinline__ void cvt4(__half* dst, const float* src, int i) {
    float4 v = ((const float4*)src)[i];
    uint2 u = make_uint2(packh2(v.x, v.y), packh2(v.z, v.w));
    *(uint2*)(dst + (size_t)i * 4) = u;
}

__global__ __launch_bounds__(256)
void convert_all(const float* x, const float* wqd, const float* wkd,
                 const float* wqu, const float* wku, const float* wv,
                 const float* wo, const float* wf1, const float* wf2) {
    for (int i = blockIdx.x * 256 + threadIdx.x; i < C8; i += gridDim.x * 256) {
        if      (i < C0) cvt4(g_x16,   x,   i);
        else if (i < C1) cvt4(g_wqd16, wqd, i - C0);
        else if (i < C2) cvt4(g_wkd16, wkd, i - C1);
        else if (i < C3) cvt4(g_wqu16, wqu, i - C2);
        else if (i < C4) cvt4(g_wku16, wku, i - C3);
        else if (i < C5) cvt4(g_wv16,  wv,  i - C4);
        else if (i < C6) cvt4(g_wo16,  wo,  i - C5);
        else if (i < C7) cvt4(g_wf116, wf1, i - C6);
        else             cvt4(g_wf216, wf2, i - C7);
    }
}

// ---------------- fp16 GEMM core: BM=64, BN=64, BK=64, 128 threads (2x2 warps) ----------------
#define GBK 64
#define GST 72
#define TBUF (64*GST)
#define GEMM_SMEM (4*TBUF*2)   // 2 stages x (A + B) = 36864 bytes

template<int ACT, typename TOUT>
__device__ __forceinline__ void gemm_core(
    const __half* __restrict__ X, const __half* __restrict__ W,
    const float* __restrict__ bias, TOUT* __restrict__ Y,
    int Ndim, int Kdim, int brow, int bcol, float os) {
    extern __shared__ __half smh[];
    const uint32_t sb = sptr(smh);

    const int tid  = threadIdx.x;
    const int lane = tid & 31, w = tid >> 5;
    const int wm = w >> 1, wn = w & 1;
    const int g = lane >> 2, t = lane & 3;
    const int nk = Kdim / GBK;

    const int offA = (wm * 32 + (lane & 15)) * GST + (lane >> 4) * 8;
    const int offB = 2 * TBUF + (wn * 32 + (lane & 7)) * GST + (lane >> 3) * 8;
    const int lr = tid >> 3, lc = (tid & 7) * 8;

    // prologue: tile 0 -> buf 0
    #pragma unroll
    for (int i = 0; i < 4; i++) {
        int r = lr + 16 * i;
        cp16(sb + (r * GST + lc) * 2, &X[(size_t)(brow + r) * Kdim + lc]);
        cp16(sb + (2 * TBUF + r * GST + lc) * 2, &W[(size_t)(bcol + r) * Kdim + lc]);
    }
    cpcommit();

    float acc[2][4][4] = {};

    for (int k = 0; k < nk; k++) {
        cpwait<0>();
        __syncthreads();
        if (k + 1 < nk) {
            int k0 = (k + 1) * GBK;
            int st = ((k + 1) & 1) * TBUF;
            #pragma unroll
            for (int i = 0; i < 4; i++) {
                int r = lr + 16 * i;
                cp16(sb + (st + r * GST + lc) * 2, &X[(size_t)(brow + r) * Kdim + k0 + lc]);
                cp16(sb + (2 * TBUF + st + r * GST + lc) * 2, &W[(size_t)(bcol + r) * Kdim + k0 + lc]);
            }
            cpcommit();
        }
        const int ab = (k & 1) * TBUF;
        const int bb = (k & 1) * TBUF;

        #pragma unroll
        for (int kg = 0; kg < 2; kg++) {
            uint32_t a[2][2][4];
            #pragma unroll
            for (int i = 0; i < 2; i++)
                #pragma unroll
                for (int ksl = 0; ksl < 2; ksl++)
                    ldsm4(a[i][ksl], sb + (ab + offA + i * 16 * GST + (kg * 2 + ksl) * 16) * 2);
            #pragma unroll
            for (int j = 0; j < 4; j++) {
                uint32_t b[4];
                ldsm4(b, sb + (bb + offB + j * 8 * GST + kg * 32) * 2);
                mma16(acc[0][j], a[0][0][0], a[0][0][1], a[0][0][2], a[0][0][3], b[0], b[1]);
                mma16(acc[1][j], a[1][0][0], a[1][0][1], a[1][0][2], a[1][0][3], b[0], b[1]);
                mma16(acc[0][j], a[0][1][0], a[0][1][1], a[0][1][2], a[0][1][3], b[2], b[3]);
                mma16(acc[1][j], a[1][1][0], a[1][1][1], a[1][1][2], a[1][1][3], b[2], b[3]);
            }
        }
    }

    #pragma unroll
    for (int i = 0; i < 2; i++) {
        int r0 = brow + wm * 32 + i * 16 + g;
        #pragma unroll
        for (int j = 0; j < 4; j++) {
            int col = bcol + wn * 32 + j * 8 + 2 * t;
            float b0 = bias[col], b1 = bias[col + 1];
            float v00 = acc[i][j][0] + b0, v01 = acc[i][j][1] + b1;
            float v10 = acc[i][j][2] + b0, v11 = acc[i][j][3] + b1;
            if (ACT) { v00 = gelu_exact(v00); v01 = gelu_exact(v01);
                       v10 = gelu_exact(v10); v11 = gelu_exact(v11); }
            st2(Y, (size_t)r0 * Ndim + col,       v00 * os, v01 * os);
            st2(Y, (size_t)(r0 + 8) * Ndim + col, v10 * os, v11 * os);
        }
    }
}

template<int ACT, typename TOUT>
__global__ __launch_bounds__(128)
void gemm_dual(const __half* __restrict__ X0, const __half* __restrict__ W0,
               const float* __restrict__ B0, TOUT* __restrict__ Y0,
               const __half* __restrict__ X1, const __half* __restrict__ W1,
               const float* __restrict__ B1, TOUT* __restrict__ Y1,
               int Ndim, int Kdim, float os0, float os1) {
    if (blockIdx.z)
        gemm_core<ACT, TOUT>(X1, W1, B1, Y1, Ndim, Kdim, blockIdx.y * 64, blockIdx.x * 64, os1);
    else
        gemm_core<ACT, TOUT>(X0, W0, B0, Y0, Ndim, Kdim, blockIdx.y * 64, blockIdx.x * 64, os0);
}

// fused [qd | kd | V] = x @ [Wqd; Wkd; Wv]^T : grid.x = 6 (0=qd, 1=kd, 2..5=V cols)
__global__ __launch_bounds__(128)
void proj_qkv(const __half* __restrict__ x16,
              const __half* __restrict__ wqd, const float* __restrict__ bqd, __half* __restrict__ qd,
              const __half* __restrict__ wkd, const float* __restrict__ bkd, __half* __restrict__ kd,
              const __half* __restrict__ wv,  const float* __restrict__ bv,  __half* __restrict__ V) {
    const int bx = blockIdx.x;
    if (bx == 0)
        gemm_core<0, __half>(x16, wqd, bqd, qd, RH, DD, blockIdx.y * 64, 0, 1.0f);
    else if (bx == 1)
        gemm_core<0, __half>(x16, wkd, bkd, kd, RH, DD, blockIdx.y * 64, 0, 1.0f);
    else
        gemm_core<0, __half>(x16, wv, bv, V, DD, DD, blockIdx.y * 64, (bx - 2) * 64, 1.0f);
}

// ---------------- flash attention: fp16, packed-f16x2 softmax, l via MMA ----------------
#define AKST 40
#define AST (64*AKST)
#define QOFF (6*AST)
#define NKT (SS / 64)
#define ONE2 0x3C003C00u

__global__ __launch_bounds__(256, 3)
void flash_attn_f16(const __half* __restrict__ Q, const __half* __restrict__ K,
                    const __half* __restrict__ V, __half* __restrict__ O) {
    __shared__ __align__(16) __half smh[QOFF + 128 * AKST];
    const uint32_t sb = sptr(smh);

    const int qt = blockIdx.x, h = blockIdx.y, b = blockIdx.z;
    const int tid = threadIdx.x, lane = tid & 31, w = tid >> 5;
    const int g = lane >> 2, t = lane & 3;

    const __half* Qb = Q + ((size_t)b * SS + (size_t)qt * 128) * DD + h * DKH;
    const __half* Kb = K + (size_t)b * SS * DD + h * DKH;
    const __half* Vb = V + (size_t)b * SS * DD + h * DKH;
    __half*       Ob = O + ((size_t)b * SS + (size_t)qt * 128) * DD + h * DKH;

    const int lr = tid >> 2, lc = (tid & 3) * 8;

    // prologue: G0 = Q + K/V tile 0; G1 = K/V tile 1
    #pragma unroll
    for (int i = 0; i < 2; i++) {
        int r = lr + 64 * i;
        cp16(sb + (QOFF + r * AKST + lc) * 2, &Qb[(size_t)r * DD + lc]);
    }
    cp16(sb + (lr * AKST + lc) * 2, &Kb[(size_t)lr * DD + lc]);
    cp16(sb + (3 * AST + lr * AKST + lc) * 2, &Vb[(size_t)lr * DD + lc]);
    cpcommit();
    cp16(sb + (AST + lr * AKST + lc) * 2, &Kb[(size_t)(64 + lr) * DD + lc]);
    cp16(sb + (4 * AST + lr * AKST + lc) * 2, &Vb[(size_t)(64 + lr) * DD + lc]);
    cpcommit();

    cpwait<1>();
    __syncthreads();

    const int offQ = QOFF + (w * 16 + (lane & 15)) * AKST + (lane >> 4) * 8;
    const int offK = (lane & 7) * AKST + (lane >> 3) * 8;
    const int offV = (((lane >> 3) & 1) * 8 + (lane & 7)) * AKST + (lane >> 4) * 8;

    // Q fragments (pre-scaled by 1/sqrt(dk)*log2e in projection epilogue)
    uint32_t qa[2][4];
    ldsm4(qa[0], sb + (offQ +  0) * 2);
    ldsm4(qa[1], sb + (offQ + 16) * 2);

    const int r0 = w * 16 + g, r1 = r0 + 8;
    float m0 = -1e30f, m1 = -1e30f;
    float acc[4][4] = {};
    float accL[4] = {};

    for (int kt = 0; kt < NKT; kt++) {
        cpwait<1>();
        __syncthreads();
        {
            int kp = kt + 2;
            if (kp < NKT) {
                int st = kp % 3;
                const __half* Kn = Kb + (size_t)kp * 64 * DD;
                const __half* Vn = Vb + (size_t)kp * 64 * DD;
                cp16(sb + (st * AST + lr * AKST + lc) * 2, &Kn[(size_t)lr * DD + lc]);
                cp16(sb + ((3 + st) * AST + lr * AKST + lc) * 2, &Vn[(size_t)lr * DD + lc]);
            }
            cpcommit();
        }
        const int kbuf = (kt % 3) * AST;
        const int vbuf = (3 + kt % 3) * AST;

        // S = Q K^T ; pack to half2 immediately (pack precedes max — only the
        // subtract needs the max)
        uint32_t plo[8], phi[8];
        #pragma unroll
        for (int j = 0; j < 8; j++) {
            uint32_t kb[4];
            ldsm4(kb, sb + (kbuf + offK + j * 8 * AKST) * 2);
            float s[4] = {0.0f, 0.0f, 0.0f, 0.0f};
            mma16(s, qa[0][0], qa[0][1], qa[0][2], qa[0][3], kb[0], kb[1]);
            mma16(s, qa[1][0], qa[1][1], qa[1][2], qa[1][3], kb[2], kb[3]);
            plo[j] = packh2(s[0], s[1]);
            phi[j] = packh2(s[2], s[3]);
        }

        // max reduction in packed f16x2 domain
        #define H2(x) (*(__half2*)&(x))
        __half2 t0 = __hmax2(__hmax2(__hmax2(H2(plo[0]), H2(plo[1])), __hmax2(H2(plo[2]), H2(plo[3]))),
                             __hmax2(__hmax2(H2(plo[4]), H2(plo[5])), __hmax2(H2(plo[6]), H2(plo[7]))));
        __half2 t1 = __hmax2(__hmax2(__hmax2(H2(phi[0]), H2(phi[1])), __hmax2(H2(phi[2]), H2(phi[3]))),
                             __hmax2(__hmax2(H2(phi[4]), H2(phi[5])), __hmax2(H2(phi[6]), H2(phi[7]))));
        __half2 mx = __hmax2(__lows2half2(t0, t1), __highs2half2(t0, t1)); // (mx0, mx1)
        {
            uint32_t u = *(uint32_t*)&mx;
            uint32_t o = __shfl_xor_sync(0xffffffffu, u, 1);
            mx = __hmax2(mx, H2(o));
            u = *(uint32_t*)&mx;
            o = __shfl_xor_sync(0xffffffffu, u, 2);
            mx = __hmax2(mx, H2(o));
        }
        float mn0 = fmaxf(m0, __low2float(mx));
        float mn1 = fmaxf(m1, __high2float(mx));
        float al0 = ex2(m0 - mn0), al1 = ex2(m1 - mn1);
        m0 = mn0; m1 = mn1;

        // p = 2^(s - mn) in f16x2; results are the packed MMA A-fragments
        const __half2 mn0h = __float2half2_rn(mn0);
        const __half2 mn1h = __float2half2_rn(mn1);
        #pragma unroll
        for (int j = 0; j < 8; j++) {
            __half2 a = __hsub2(H2(plo[j]), mn0h);
            __half2 c = __hsub2(H2(phi[j]), mn1h);
            plo[j] = h2ex2(*(uint32_t*)&a);
            phi[j] = h2ex2(*(uint32_t*)&c);
        }
        #undef H2

        // rescale accumulators
        #pragma unroll
        for (int j = 0; j < 4; j++) {
            acc[j][0] *= al0; acc[j][1] *= al0;
            acc[j][2] *= al1; acc[j][3] *= al1;
        }
        accL[0] *= al0; accL[2] *= al1;

        // PV + row-sum: O += P*V, accL += P*ones
        #pragma unroll
        for (int ks = 0; ks < 4; ks++) {
            uint32_t v0[4], v1[4];
            ldsm4t(v0, sb + (vbuf + offV + ks * 16 * AKST) * 2);
            ldsm4t(v1, sb + (vbuf + offV + ks * 16 * AKST + 16) * 2);
            uint32_t a0 = plo[2 * ks], a1 = phi[2 * ks];
            uint32_t a2 = plo[2 * ks + 1], a3 = phi[2 * ks + 1];
            mma16(acc[0], a0, a1, a2, a3, v0[0], v0[1]);
            mma16(acc[1], a0, a1, a2, a3, v0[2], v0[3]);
            mma16(acc[2], a0, a1, a2, a3, v1[0], v1[1]);
            mma16(acc[3], a0, a1, a2, a3, v1[2], v1[3]);
            mma16(accL, a0, a1, a2, a3, ONE2, ONE2);
        }
    }

    const float il0 = 1.0f / accL[0], il1 = 1.0f / accL[2];
    #pragma unroll
    for (int j = 0; j < 4; j++) {
        int col = j * 8 + 2 * t;
        st2(Ob, (size_t)r0 * DD + col, acc[j][0] * il0, acc[j][1] * il0);
        st2(Ob, (size_t)r1 * DD + col, acc[j][2] * il1, acc[j][3] * il1);
    }
}

// ---------------- fused residual + LayerNorm ----------------
template<int W16>
__global__ __launch_bounds__(256)
void ln_residual(const float* __restrict__ X, const float* __restrict__ R,
                 const float* __restrict__ g, const float* __restrict__ bta,
                 float* __restrict__ Y, __half* __restrict__ Y16) {
    int row  = blockIdx.x * 8 + (threadIdx.x >> 5);
    int lane = threadIdx.x & 31;
    const float4* x4 = (const float4*)(X + (size_t)row * DD);
    const float4* r4 = (const float4*)(R + (size_t)row * DD);

    float4 v[2];
    float sum = 0.0f;
    #pragma unroll
    for (int k = 0; k < 2; k++) {
        float4 a = x4[lane + 32 * k], b = r4[lane + 32 * k];
        v[k] = make_float4(a.x + b.x, a.y + b.y, a.z + b.z, a.w + b.w);
        sum += v[k].x + v[k].y + v[k].z + v[k].w;
    }
    #pragma unroll
    for (int o = 16; o > 0; o >>= 1) sum += __shfl_xor_sync(0xffffffffu, sum, o);
    float mu = sum * (1.0f / 256.0f);

    float vs = 0.0f;
    #pragma unroll
    for (int k = 0; k < 2; k++) {
        float dx = v[k].x - mu, dy = v[k].y - mu, dz = v[k].z - mu, dw = v[k].w - mu;
        vs = fmaf(dx, dx, vs); vs = fmaf(dy, dy, vs);
        vs = fmaf(dz, dz, vs); vs = fmaf(dw, dw, vs);
    }
    #pragma unroll
    for (int o = 16; o > 0; o >>= 1) vs += __shfl_xor_sync(0xffffffffu, vs, o);
    float rstd = rsqrtf(vs * (1.0f / 256.0f) + 1e-5f);

    const float4* g4 = (const float4*)g;
    const float4* b4 = (const float4*)bta;
    float4* y4 = (float4*)(Y + (size_t)row * DD);
    #pragma unroll
    for (int k = 0; k < 2; k++) {
        float4 gg = g4[lane + 32 * k], bb = b4[lane + 32 * k];
        float4 o;
        o.x = (v[k].x - mu) * rstd * gg.x + bb.x;
        o.y = (v[k].y - mu) * rstd * gg.y + bb.y;
        o.z = (v[k].z - mu) * rstd * gg.z + bb.z;
        o.w = (v[k].w - mu) * rstd * gg.w + bb.w;
        y4[lane + 32 * k] = o;
        if (W16) {
            int col = (lane + 32 * k) * 4;
            uint2 u = make_uint2(packh2(o.x, o.y), packh2(o.z, o.w));
            *(uint2*)(Y16 + (size_t)row * DD + col) = u;
        }
    }
}

// ---------------- launch ----------------
extern "C" void kernel_launch(void* const* d_in, const int* in_sizes, int n_in,
                              void* d_out, int out_size) {
    const float* x       = (const float*)d_in[0];
    const float* Wq_down = (const float*)d_in[1];
    const float* bq_down = (const float*)d_in[2];
    const float* Wq_up   = (const float*)d_in[3];
    const float* bq_up   = (const float*)d_in[4];
    const float* Wk_down = (const float*)d_in[5];
    const float* bk_down = (const float*)d_in[6];
    const float* Wk_up   = (const float*)d_in[7];
    const float* bk_up   = (const float*)d_in[8];
    const float* Wv      = (const float*)d_in[9];
    const float* bv      = (const float*)d_in[10];
    const float* Wo      = (const float*)d_in[11];
    const float* bo      = (const float*)d_in[12];
    const float* ln_a_g  = (const float*)d_in[13];
    const float* ln_a_b  = (const float*)d_in[14];
    const float* W_ff1   = (const float*)d_in[15];
    const float* b_ff1   = (const float*)d_in[16];
    const float* W_ff2   = (const float*)d_in[17];
    const float* b_ff2   = (const float*)d_in[18];
    const float* ln_b_g  = (const float*)d_in[19];
    const float* ln_b_b  = (const float*)d_in[20];
    float* out = (float*)d_out;

    __half *x16, *wqd16, *wkd16, *wqu16, *wku16, *wv16, *wo16, *wf116, *wf216;
    __half *qd16, *kd16, *Q16, *K16, *V16, *ctx16, *ln116, *h16;
    float *ao, *ln1, *ff;
    cudaGetSymbolAddress((void**)&x16,   g_x16);
    cudaGetSymbolAddress((void**)&wqd16, g_wqd16);
    cudaGetSymbolAddress((void**)&wkd16, g_wkd16);
    cudaGetSymbolAddress((void**)&wqu16, g_wqu16);
    cudaGetSymbolAddress((void**)&wku16, g_wku16);
    cudaGetSymbolAddress((void**)&wv16,  g_wv16);
    cudaGetSymbolAddress((void**)&wo16,  g_wo16);
    cudaGetSymbolAddress((void**)&wf116, g_wf116);
    cudaGetSymbolAddress((void**)&wf216, g_wf216);
    cudaGetSymbolAddress((void**)&qd16,  g_qd16);
    cudaGetSymbolAddress((void**)&kd16,  g_kd16);
    cudaGetSymbolAddress((void**)&Q16,   g_Q16);
    cudaGetSymbolAddress((void**)&K16,   g_K16);
    cudaGetSymbolAddress((void**)&V16,   g_V16);
    cudaGetSymbolAddress((void**)&ctx16, g_ctx16);
    cudaGetSymbolAddress((void**)&ln116, g_ln116);
    cudaGetSymbolAddress((void**)&h16,   g_h16);
    cudaGetSymbolAddress((void**)&ao,    g_ao);
    cudaGetSymbolAddress((void**)&ln1,   g_ln1);
    cudaGetSymbolAddress((void**)&ff,    g_ff);

    const float scale2 = 0.17677669529663687f * 1.4426950408889634f;

    convert_all<<<512, 256>>>(x, Wq_down, Wk_down, Wq_up, Wk_up, Wv, Wo, W_ff1, W_ff2);
    // fused [qd | kd | V] (all K=256 from x16)
    proj_qkv<<<dim3(6, MM / 64), 128, GEMM_SMEM>>>(
        x16, wqd16, bq_down, qd16, wkd16, bk_down, kd16, wv16, bv, V16);
    // fused Q/K up-projections (N=256, K=64); Q pre-scaled for softmax
    gemm_dual<0, __half><<<dim3(4, MM / 64, 2), 128, GEMM_SMEM>>>(
        qd16, wqu16, bq_up, Q16,  kd16, wku16, bk_up, K16, DD, RH, scale2, 1.0f);
    // attention
    flash_attn_f16<<<dim3(SS / 128, HH, BB), 256>>>(Q16, K16, V16, ctx16);
    // output projection (fp32 out -> LN residual)
    gemm_dual<0, float><<<dim3(4, MM / 64, 1), 128, GEMM_SMEM>>>(
        ctx16, wo16, bo, ao,  ctx16, wo16, bo, ao, DD, DD, 1.0f, 1.0f);
    // LN(x + attn_out) -> fp32 + fp16
    ln_residual<1><<<MM / 8, 256>>>(x, ao, ln_a_g, ln_a_b, ln1, ln116);
    // FFN
    gemm_dual<1, __half><<<dim3(DFFC / 64, MM / 64, 1), 128, GEMM_SMEM>>>(
        ln116, wf116, b_ff1, h16,  ln116, wf116, b_ff1, h16, DFFC, DD, 1.0f, 1.0f);
    gemm_dual<0, float><<<dim3(4, MM / 64, 1), 128, GEMM_SMEM>>>(
        h16, wf216, b_ff2, ff,  h16, wf216, b_ff2, ff, DD, DFFC, 1.0f, 1.0f);
    // final LN
    ln_residual<0><<<MM / 8, 256>>>(ln1, ff, ln_b_g, ln_b_b, out, (__half*)nullptr);
}

// round 8
// speedup vs baseline: 9.5639x; 1.0413x over previous
#include <cuda_runtime.h>
#include <cuda_fp16.h>
#include <math.h>
#include <stdint.h>

// Problem constants
#define BB   4
#define SS   2048
#define DD   256
#define HH   8
#define DKH  32
#define RH   64          // RANK*H
#define DFFC 1024
#define MM   (BB*SS)     // 8192 rows

// ---------------- scratch (no allocs allowed) ----------------
__device__ __align__(16) __half g_x16 [MM*DD];
__device__ __align__(16) __half g_wqd16[RH*DD];
__device__ __align__(16) __half g_wkd16[RH*DD];
__device__ __align__(16) __half g_wqu16[DD*RH];
__device__ __align__(16) __half g_wku16[DD*RH];
__device__ __align__(16) __half g_wv16 [DD*DD];
__device__ __align__(16) __half g_wo16 [DD*DD];
__device__ __align__(16) __half g_wf116[DFFC*DD];
__device__ __align__(16) __half g_wf216[DD*DFFC];
__device__ __align__(16) __half g_qd16 [MM*RH];
__device__ __align__(16) __half g_kd16 [MM*RH];
__device__ __align__(16) __half g_Q16  [MM*DD];
__device__ __align__(16) __half g_K16  [MM*DD];
__device__ __align__(16) __half g_V16  [MM*DD];
__device__ __align__(16) __half g_ctx16[MM*DD];
__device__ __align__(16) __half g_ln116[MM*DD];
__device__ __align__(16) __half g_h16  [MM*DFFC];
__device__ float g_ao [MM*DD];
__device__ float g_ln1[MM*DD];
__device__ float g_ff [MM*DD];

// ---------------- helpers ----------------
__device__ __forceinline__ uint32_t sptr(const void* p) {
    return (uint32_t)__cvta_generic_to_shared(p);
}
__device__ __forceinline__ void cp16(uint32_t s, const void* g) {
    asm volatile("cp.async.cg.shared.global [%0], [%1], 16;\n" :: "r"(s), "l"(g));
}
__device__ __forceinline__ void cpcommit() {
    asm volatile("cp.async.commit_group;\n" ::: "memory");
}
template<int N> __device__ __forceinline__ void cpwait() {
    asm volatile("cp.async.wait_group %0;\n" :: "n"(N) : "memory");
}
__device__ __forceinline__ void ldsm4(uint32_t* r, uint32_t addr) {
    asm volatile("ldmatrix.sync.aligned.m8n8.x4.shared.b16 {%0,%1,%2,%3}, [%4];"
                 : "=r"(r[0]), "=r"(r[1]), "=r"(r[2]), "=r"(r[3]) : "r"(addr));
}
__device__ __forceinline__ void ldsm4t(uint32_t* r, uint32_t addr) {
    asm volatile("ldmatrix.sync.aligned.m8n8.x4.trans.shared.b16 {%0,%1,%2,%3}, [%4];"
                 : "=r"(r[0]), "=r"(r[1]), "=r"(r[2]), "=r"(r[3]) : "r"(addr));
}
__device__ __forceinline__ void mma16(float* c, uint32_t a0, uint32_t a1,
                                      uint32_t a2, uint32_t a3,
                                      uint32_t b0, uint32_t b1) {
    asm volatile(
        "mma.sync.aligned.m16n8k16.row.col.f32.f16.f16.f32 "
        "{%0,%1,%2,%3},{%4,%5,%6,%7},{%8,%9},{%0,%1,%2,%3};"
        : "+f"(c[0]), "+f"(c[1]), "+f"(c[2]), "+f"(c[3])
        : "r"(a0), "r"(a1), "r"(a2), "r"(a3), "r"(b0), "r"(b1));
}
__device__ __forceinline__ float ex2(float x) {
    float r; asm("ex2.approx.f32 %0, %1;" : "=f"(r) : "f"(x)); return r;
}
__device__ __forceinline__ uint32_t h2ex2(uint32_t x) {
    uint32_t r; asm("ex2.approx.f16x2 %0, %1;" : "=r"(r) : "r"(x)); return r;
}
__device__ __forceinline__ uint32_t packh2(float lo, float hi) {
    __half2 h = __floats2half2_rn(lo, hi);
    return *(uint32_t*)&h;
}
__device__ __forceinline__ float gelu_exact(float x) {
    return 0.5f * x * (1.0f + erff(x * 0.70710678118654752f));
}
__device__ __forceinline__ void st2(float* Y, size_t idx, float a, float b) {
    *(float2*)&Y[idx] = make_float2(a, b);
}
__device__ __forceinline__ void st2(__half* Y, size_t idx, float a, float b) {
    *(__half2*)&Y[idx] = __floats2half2_rn(a, b);
}

// ---------------- fp32 -> fp16 conversion ----------------
#define F4_X   (MM*DD/4)
#define F4_SM  (RH*DD/4)
#define F4_WV  (DD*DD/4)
#define F4_FF  (DFFC*DD/4)
#define C0 F4_X
#define C1 (C0+F4_SM)
#define C2 (C1+F4_SM)
#define C3 (C2+F4_SM)
#define C4 (C3+F4_SM)
#define C5 (C4+F4_WV)
#define C6 (C5+F4_WV)
#define C7 (C6+F4_FF)
#define C8 (C7+F4_FF)

__device__ __forceinline__ void cvt4(__half* dst, const float* src, int i) {
    float4 v = ((const float4*)src)[i];
    uint2 u = make_uint2(packh2(v.x, v.y), packh2(v.z, v.w));
    *(uint2*)(dst + (size_t)i * 4) = u;
}

__global__ __launch_bounds__(256)
void convert_all(const float* x, const float* wqd, const float* wkd,
                 const float* wqu, const float* wku, const float* wv,
                 const float* wo, const float* wf1, const float* wf2) {
    for (int i = blockIdx.x * 256 + threadIdx.x; i < C8; i += gridDim.x * 256) {
        if      (i < C0) cvt4(g_x16,   x,   i);
        else if (i < C1) cvt4(g_wqd16, wqd, i - C0);
        else if (i < C2) cvt4(g_wkd16, wkd, i - C1);
        else if (i < C3) cvt4(g_wqu16, wqu, i - C2);
        else if (i < C4) cvt4(g_wku16, wku, i - C3);
        else if (i < C5) cvt4(g_wv16,  wv,  i - C4);
        else if (i < C6) cvt4(g_wo16,  wo,  i - C5);
        else if (i < C7) cvt4(g_wf116, wf1, i - C6);
        else             cvt4(g_wf216, wf2, i - C7);
    }
}

// ---------------- fp16 GEMM core: BM=64, BN=64, BK=64, 128 threads (2x2 warps) ----------------
#define GBK 64
#define GST 72
#define TBUF (64*GST)
#define GEMM_SMEM (4*TBUF*2)   // 2 stages x (A + B) = 36864 bytes

template<int ACT, typename TOUT>
__device__ __forceinline__ void gemm_core(
    const __half* __restrict__ X, const __half* __restrict__ W,
    const float* __restrict__ bias, TOUT* __restrict__ Y,
    int Ndim, int Kdim, int brow, int bcol, float os) {
    extern __shared__ __half smh[];
    const uint32_t sb = sptr(smh);

    const int tid  = threadIdx.x;
    const int lane = tid & 31, w = tid >> 5;
    const int wm = w >> 1, wn = w & 1;
    const int g = lane >> 2, t = lane & 3;
    const int nk = Kdim / GBK;

    const int offA = (wm * 32 + (lane & 15)) * GST + (lane >> 4) * 8;
    const int offB = 2 * TBUF + (wn * 32 + (lane & 7)) * GST + (lane >> 3) * 8;
    const int lr = tid >> 3, lc = (tid & 7) * 8;

    // prologue: tile 0 -> buf 0
    #pragma unroll
    for (int i = 0; i < 4; i++) {
        int r = lr + 16 * i;
        cp16(sb + (r * GST + lc) * 2, &X[(size_t)(brow + r) * Kdim + lc]);
        cp16(sb + (2 * TBUF + r * GST + lc) * 2, &W[(size_t)(bcol + r) * Kdim + lc]);
    }
    cpcommit();

    float acc[2][4][4] = {};

    for (int k = 0; k < nk; k++) {
        cpwait<0>();
        __syncthreads();
        if (k + 1 < nk) {
            int k0 = (k + 1) * GBK;
            int st = ((k + 1) & 1) * TBUF;
            #pragma unroll
            for (int i = 0; i < 4; i++) {
                int r = lr + 16 * i;
                cp16(sb + (st + r * GST + lc) * 2, &X[(size_t)(brow + r) * Kdim + k0 + lc]);
                cp16(sb + (2 * TBUF + st + r * GST + lc) * 2, &W[(size_t)(bcol + r) * Kdim + k0 + lc]);
            }
            cpcommit();
        }
        const int ab = (k & 1) * TBUF;
        const int bb = (k & 1) * TBUF;

        #pragma unroll
        for (int kg = 0; kg < 2; kg++) {
            uint32_t a[2][2][4];
            #pragma unroll
            for (int i = 0; i < 2; i++)
                #pragma unroll
                for (int ksl = 0; ksl < 2; ksl++)
                    ldsm4(a[i][ksl], sb + (ab + offA + i * 16 * GST + (kg * 2 + ksl) * 16) * 2);
            #pragma unroll
            for (int j = 0; j < 4; j++) {
                uint32_t b[4];
                ldsm4(b, sb + (bb + offB + j * 8 * GST + kg * 32) * 2);
                mma16(acc[0][j], a[0][0][0], a[0][0][1], a[0][0][2], a[0][0][3], b[0], b[1]);
                mma16(acc[1][j], a[1][0][0], a[1][0][1], a[1][0][2], a[1][0][3], b[0], b[1]);
                mma16(acc[0][j], a[0][1][0], a[0][1][1], a[0][1][2], a[0][1][3], b[2], b[3]);
                mma16(acc[1][j], a[1][1][0], a[1][1][1], a[1][1][2], a[1][1][3], b[2], b[3]);
            }
        }
    }

    #pragma unroll
    for (int i = 0; i < 2; i++) {
        int r0 = brow + wm * 32 + i * 16 + g;
        #pragma unroll
        for (int j = 0; j < 4; j++) {
            int col = bcol + wn * 32 + j * 8 + 2 * t;
            float b0 = bias[col], b1 = bias[col + 1];
            float v00 = acc[i][j][0] + b0, v01 = acc[i][j][1] + b1;
            float v10 = acc[i][j][2] + b0, v11 = acc[i][j][3] + b1;
            if (ACT) { v00 = gelu_exact(v00); v01 = gelu_exact(v01);
                       v10 = gelu_exact(v10); v11 = gelu_exact(v11); }
            st2(Y, (size_t)r0 * Ndim + col,       v00 * os, v01 * os);
            st2(Y, (size_t)(r0 + 8) * Ndim + col, v10 * os, v11 * os);
        }
    }
}

template<int ACT, typename TOUT>
__global__ __launch_bounds__(128)
void gemm_dual(const __half* __restrict__ X0, const __half* __restrict__ W0,
               const float* __restrict__ B0, TOUT* __restrict__ Y0,
               const __half* __restrict__ X1, const __half* __restrict__ W1,
               const float* __restrict__ B1, TOUT* __restrict__ Y1,
               int Ndim, int Kdim, float os0, float os1) {
    if (blockIdx.z)
        gemm_core<ACT, TOUT>(X1, W1, B1, Y1, Ndim, Kdim, blockIdx.y * 64, blockIdx.x * 64, os1);
    else
        gemm_core<ACT, TOUT>(X0, W0, B0, Y0, Ndim, Kdim, blockIdx.y * 64, blockIdx.x * 64, os0);
}

// fused [qd | kd | V] = x @ [Wqd; Wkd; Wv]^T : grid.x = 6 (0=qd, 1=kd, 2..5=V cols)
__global__ __launch_bounds__(128)
void proj_qkv(const __half* __restrict__ x16,
              const __half* __restrict__ wqd, const float* __restrict__ bqd, __half* __restrict__ qd,
              const __half* __restrict__ wkd, const float* __restrict__ bkd, __half* __restrict__ kd,
              const __half* __restrict__ wv,  const float* __restrict__ bv,  __half* __restrict__ V) {
    const int bx = blockIdx.x;
    if (bx == 0)
        gemm_core<0, __half>(x16, wqd, bqd, qd, RH, DD, blockIdx.y * 64, 0, 1.0f);
    else if (bx == 1)
        gemm_core<0, __half>(x16, wkd, bkd, kd, RH, DD, blockIdx.y * 64, 0, 1.0f);
    else
        gemm_core<0, __half>(x16, wv, bv, V, DD, DD, blockIdx.y * 64, (bx - 2) * 64, 1.0f);
}

// ---------------- flash attention: BQ=64, 128 threads, 4 warps ----------------
#define AKST 40
#define AST (64*AKST)
#define AST2 (AST*2)         // stage size in bytes
#define QOFF (6*AST)
#define NKT (SS / 64)
#define ONE2 0x3C003C00u

__global__ __launch_bounds__(128)
void flash_attn_f16(const __half* __restrict__ Q, const __half* __restrict__ K,
                    const __half* __restrict__ V, __half* __restrict__ O) {
    __shared__ __align__(16) __half smh[QOFF + 64 * AKST];
    const uint32_t sb = sptr(smh);

    const int qt = blockIdx.x, h = blockIdx.y, b = blockIdx.z;
    const int tid = threadIdx.x, lane = tid & 31, w = tid >> 5;
    const int g = lane >> 2, t = lane & 3;

    const __half* Qb = Q + ((size_t)b * SS + (size_t)qt * 64) * DD + h * DKH;
    const __half* Kb = K + (size_t)b * SS * DD + h * DKH;
    const __half* Vb = V + (size_t)b * SS * DD + h * DKH;
    __half*       Ob = O + ((size_t)b * SS + (size_t)qt * 64) * DD + h * DKH;

    const int lr = tid >> 2, lc = (tid & 3) * 8;   // 32 rows per pass, 4 thr/row

    // prologue: Q (64x32) + K/V tiles 0,1
    #pragma unroll
    for (int i = 0; i < 2; i++) {
        int r = lr + 32 * i;
        cp16(sb + (QOFF + r * AKST + lc) * 2, &Qb[(size_t)r * DD + lc]);
        cp16(sb + (r * AKST + lc) * 2, &Kb[(size_t)r * DD + lc]);
        cp16(sb + (3 * AST + r * AKST + lc) * 2, &Vb[(size_t)r * DD + lc]);
    }
    cpcommit();
    #pragma unroll
    for (int i = 0; i < 2; i++) {
        int r = lr + 32 * i;
        cp16(sb + (AST + r * AKST + lc) * 2, &Kb[(size_t)(64 + r) * DD + lc]);
        cp16(sb + (4 * AST + r * AKST + lc) * 2, &Vb[(size_t)(64 + r) * DD + lc]);
    }
    cpcommit();

    cpwait<1>();
    __syncthreads();

    const int offQ = QOFF + (w * 16 + (lane & 15)) * AKST + (lane >> 4) * 8;
    const int offK = (lane & 7) * AKST + (lane >> 3) * 8;
    const int offV = (((lane >> 3) & 1) * 8 + (lane & 7)) * AKST + (lane >> 4) * 8;

    // Q fragments (pre-scaled by 1/sqrt(dk)*log2e in projection epilogue)
    uint32_t qa[2][4];
    ldsm4(qa[0], sb + (offQ +  0) * 2);
    ldsm4(qa[1], sb + (offQ + 16) * 2);

    // cycling stage byte-offsets (no %3 in the loop)
    const uint32_t kbase = sb + offK * 2;
    const uint32_t vbase = sb + 3 * AST2 + offV * 2;
    const uint32_t pkbase = sb + (lr * AKST + lc) * 2;
    const uint32_t pvbase = pkbase + 3 * AST2;
    uint32_t cur = 0;          // stage of tile kt
    uint32_t pre = 2 * AST2;   // stage of tile kt+2 (write target)

    const int r0 = w * 16 + g, r1 = r0 + 8;
    float m0 = -1e30f, m1 = -1e30f;
    float acc[4][4] = {};
    float accL[4] = {};

    for (int kt = 0; kt < NKT; kt++) {
        cpwait<1>();
        __syncthreads();
        {
            int kp = kt + 2;
            if (kp < NKT) {
                const __half* Kn = Kb + (size_t)kp * 64 * DD;
                const __half* Vn = Vb + (size_t)kp * 64 * DD;
                #pragma unroll
                for (int i = 0; i < 2; i++) {
                    uint32_t ro = i * 32 * AKST * 2;
                    size_t go = (size_t)(lr + 32 * i) * DD + lc;
                    cp16(pkbase + pre + ro, &Kn[go]);
                    cp16(pvbase + pre + ro, &Vn[go]);
                }
            }
            cpcommit();
        }
        const uint32_t kaddr = kbase + cur;
        const uint32_t vaddr = vbase + cur;

        // S = Q K^T ; pack to half2 immediately
        uint32_t plo[8], phi[8];
        #pragma unroll
        for (int j = 0; j < 8; j++) {
            uint32_t kb[4];
            ldsm4(kb, kaddr + j * 8 * AKST * 2);
            float s[4] = {0.0f, 0.0f, 0.0f, 0.0f};
            mma16(s, qa[0][0], qa[0][1], qa[0][2], qa[0][3], kb[0], kb[1]);
            mma16(s, qa[1][0], qa[1][1], qa[1][2], qa[1][3], kb[2], kb[3]);
            plo[j] = packh2(s[0], s[1]);
            phi[j] = packh2(s[2], s[3]);
        }

        // max reduction in packed f16x2 domain
        #define H2(x) (*(__half2*)&(x))
        __half2 t0 = __hmax2(__hmax2(__hmax2(H2(plo[0]), H2(plo[1])), __hmax2(H2(plo[2]), H2(plo[3]))),
                             __hmax2(__hmax2(H2(plo[4]), H2(plo[5])), __hmax2(H2(plo[6]), H2(plo[7]))));
        __half2 t1 = __hmax2(__hmax2(__hmax2(H2(phi[0]), H2(phi[1])), __hmax2(H2(phi[2]), H2(phi[3]))),
                             __hmax2(__hmax2(H2(phi[4]), H2(phi[5])), __hmax2(H2(phi[6]), H2(phi[7]))));
        __half2 mx = __hmax2(__lows2half2(t0, t1), __highs2half2(t0, t1)); // (mx0, mx1)
        {
            uint32_t u = *(uint32_t*)&mx;
            uint32_t o = __shfl_xor_sync(0xffffffffu, u, 1);
            mx = __hmax2(mx, H2(o));
            u = *(uint32_t*)&mx;
            o = __shfl_xor_sync(0xffffffffu, u, 2);
            mx = __hmax2(mx, H2(o));
        }
        float mn0 = fmaxf(m0, __low2float(mx));
        float mn1 = fmaxf(m1, __high2float(mx));
        float al0 = ex2(m0 - mn0), al1 = ex2(m1 - mn1);
        m0 = mn0; m1 = mn1;

        // p = 2^(s - mn) in f16x2; results are the packed MMA A-fragments
        const __half2 mn0h = __float2half2_rn(mn0);
        const __half2 mn1h = __float2half2_rn(mn1);
        #pragma unroll
        for (int j = 0; j < 8; j++) {
            __half2 a = __hsub2(H2(plo[j]), mn0h);
            __half2 c = __hsub2(H2(phi[j]), mn1h);
            plo[j] = h2ex2(*(uint32_t*)&a);
            phi[j] = h2ex2(*(uint32_t*)&c);
        }
        #undef H2

        // rescale accumulators
        #pragma unroll
        for (int j = 0; j < 4; j++) {
            acc[j][0] *= al0; acc[j][1] *= al0;
            acc[j][2] *= al1; acc[j][3] *= al1;
        }
        accL[0] *= al0; accL[2] *= al1;

        // PV + row-sum: O += P*V, accL += P*ones
        #pragma unroll
        for (int ks = 0; ks < 4; ks++) {
            uint32_t v0[4], v1[4];
            ldsm4t(v0, vaddr + ks * 16 * AKST * 2);
            ldsm4t(v1, vaddr + (ks * 16 * AKST + 16) * 2);
            uint32_t a0 = plo[2 * ks], a1 = phi[2 * ks];
            uint32_t a2 = plo[2 * ks + 1], a3 = phi[2 * ks + 1];
            mma16(acc[0], a0, a1, a2, a3, v0[0], v0[1]);
            mma16(acc[1], a0, a1, a2, a3, v0[2], v0[3]);
            mma16(acc[2], a0, a1, a2, a3, v1[0], v1[1]);
            mma16(acc[3], a0, a1, a2, a3, v1[2], v1[3]);
            mma16(accL, a0, a1, a2, a3, ONE2, ONE2);
        }

        cur += AST2; if (cur == 3 * AST2) cur = 0;
        pre += AST2; if (pre == 3 * AST2) pre = 0;
    }

    const float il0 = 1.0f / accL[0], il1 = 1.0f / accL[2];
    #pragma unroll
    for (int j = 0; j < 4; j++) {
        int col = j * 8 + 2 * t;
        st2(Ob, (size_t)r0 * DD + col, acc[j][0] * il0, acc[j][1] * il0);
        st2(Ob, (size_t)r1 * DD + col, acc[j][2] * il1, acc[j][3] * il1);
    }
}

// ---------------- fused residual + LayerNorm ----------------
template<int W16>
__global__ __launch_bounds__(256)
void ln_residual(const float* __restrict__ X, const float* __restrict__ R,
                 const float* __restrict__ g, const float* __restrict__ bta,
                 float* __restrict__ Y, __half* __restrict__ Y16) {
    int row  = blockIdx.x * 8 + (threadIdx.x >> 5);
    int lane = threadIdx.x & 31;
    const float4* x4 = (const float4*)(X + (size_t)row * DD);
    const float4* r4 = (const float4*)(R + (size_t)row * DD);

    float4 v[2];
    float sum = 0.0f;
    #pragma unroll
    for (int k = 0; k < 2; k++) {
        float4 a = x4[lane + 32 * k], b = r4[lane + 32 * k];
        v[k] = make_float4(a.x + b.x, a.y + b.y, a.z + b.z, a.w + b.w);
        sum += v[k].x + v[k].y + v[k].z + v[k].w;
    }
    #pragma unroll
    for (int o = 16; o > 0; o >>= 1) sum += __shfl_xor_sync(0xffffffffu, sum, o);
    float mu = sum * (1.0f / 256.0f);

    float vs = 0.0f;
    #pragma unroll
    for (int k = 0; k < 2; k++) {
        float dx = v[k].x - mu, dy = v[k].y - mu, dz = v[k].z - mu, dw = v[k].w - mu;
        vs = fmaf(dx, dx, vs); vs = fmaf(dy, dy, vs);
        vs = fmaf(dz, dz, vs); vs = fmaf(dw, dw, vs);
    }
    #pragma unroll
    for (int o = 16; o > 0; o >>= 1) vs += __shfl_xor_sync(0xffffffffu, vs, o);
    float rstd = rsqrtf(vs * (1.0f / 256.0f) + 1e-5f);

    const float4* g4 = (const float4*)g;
    const float4* b4 = (const float4*)bta;
    float4* y4 = (float4*)(Y + (size_t)row * DD);
    #pragma unroll
    for (int k = 0; k < 2; k++) {
        float4 gg = g4[lane + 32 * k], bb = b4[lane + 32 * k];
        float4 o;
        o.x = (v[k].x - mu) * rstd * gg.x + bb.x;
        o.y = (v[k].y - mu) * rstd * gg.y + bb.y;
        o.z = (v[k].z - mu) * rstd * gg.z + bb.z;
        o.w = (v[k].w - mu) * rstd * gg.w + bb.w;
        y4[lane + 32 * k] = o;
        if (W16) {
            int col = (lane + 32 * k) * 4;
            uint2 u = make_uint2(packh2(o.x, o.y), packh2(o.z, o.w));
            *(uint2*)(Y16 + (size_t)row * DD + col) = u;
        }
    }
}

// ---------------- launch ----------------
extern "C" void kernel_launch(void* const* d_in, const int* in_sizes, int n_in,
                              void* d_out, int out_size) {
    const float* x       = (const float*)d_in[0];
    const float* Wq_down = (const float*)d_in[1];
    const float* bq_down = (const float*)d_in[2];
    const float* Wq_up   = (const float*)d_in[3];
    const float* bq_up   = (const float*)d_in[4];
    const float* Wk_down = (const float*)d_in[5];
    const float* bk_down = (const float*)d_in[6];
    const float* Wk_up   = (const float*)d_in[7];
    const float* bk_up   = (const float*)d_in[8];
    const float* Wv      = (const float*)d_in[9];
    const float* bv      = (const float*)d_in[10];
    const float* Wo      = (const float*)d_in[11];
    const float* bo      = (const float*)d_in[12];
    const float* ln_a_g  = (const float*)d_in[13];
    const float* ln_a_b  = (const float*)d_in[14];
    const float* W_ff1   = (const float*)d_in[15];
    const float* b_ff1   = (const float*)d_in[16];
    const float* W_ff2   = (const float*)d_in[17];
    const float* b_ff2   = (const float*)d_in[18];
    const float* ln_b_g  = (const float*)d_in[19];
    const float* ln_b_b  = (const float*)d_in[20];
    float* out = (float*)d_out;

    __half *x16, *wqd16, *wkd16, *wqu16, *wku16, *wv16, *wo16, *wf116, *wf216;
    __half *qd16, *kd16, *Q16, *K16, *V16, *ctx16, *ln116, *h16;
    float *ao, *ln1, *ff;
    cudaGetSymbolAddress((void**)&x16,   g_x16);
    cudaGetSymbolAddress((void**)&wqd16, g_wqd16);
    cudaGetSymbolAddress((void**)&wkd16, g_wkd16);
    cudaGetSymbolAddress((void**)&wqu16, g_wqu16);
    cudaGetSymbolAddress((void**)&wku16, g_wku16);
    cudaGetSymbolAddress((void**)&wv16,  g_wv16);
    cudaGetSymbolAddress((void**)&wo16,  g_wo16);
    cudaGetSymbolAddress((void**)&wf116, g_wf116);
    cudaGetSymbolAddress((void**)&wf216, g_wf216);
    cudaGetSymbolAddress((void**)&qd16,  g_qd16);
    cudaGetSymbolAddress((void**)&kd16,  g_kd16);
    cudaGetSymbolAddress((void**)&Q16,   g_Q16);
    cudaGetSymbolAddress((void**)&K16,   g_K16);
    cudaGetSymbolAddress((void**)&V16,   g_V16);
    cudaGetSymbolAddress((void**)&ctx16, g_ctx16);
    cudaGetSymbolAddress((void**)&ln116, g_ln116);
    cudaGetSymbolAddress((void**)&h16,   g_h16);
    cudaGetSymbolAddress((void**)&ao,    g_ao);
    cudaGetSymbolAddress((void**)&ln1,   g_ln1);
    cudaGetSymbolAddress((void**)&ff,    g_ff);

    const float scale2 = 0.17677669529663687f * 1.4426950408889634f;

    convert_all<<<512, 256>>>(x, Wq_down, Wk_down, Wq_up, Wk_up, Wv, Wo, W_ff1, W_ff2);
    // fused [qd | kd | V] (all K=256 from x16)
    proj_qkv<<<dim3(6, MM / 64), 128, GEMM_SMEM>>>(
        x16, wqd16, bq_down, qd16, wkd16, bk_down, kd16, wv16, bv, V16);
    // fused Q/K up-projections (N=256, K=64); Q pre-scaled for softmax
    gemm_dual<0, __half><<<dim3(4, MM / 64, 2), 128, GEMM_SMEM>>>(
        qd16, wqu16, bq_up, Q16,  kd16, wku16, bk_up, K16, DD, RH, scale2, 1.0f);
    // attention (BQ=64, 128 threads)
    flash_attn_f16<<<dim3(SS / 64, HH, BB), 128>>>(Q16, K16, V16, ctx16);
    // output projection (fp32 out -> LN residual)
    gemm_dual<0, float><<<dim3(4, MM / 64, 1), 128, GEMM_SMEM>>>(
        ctx16, wo16, bo, ao,  ctx16, wo16, bo, ao, DD, DD, 1.0f, 1.0f);
    // LN(x + attn_out) -> fp32 + fp16
    ln_residual<1><<<MM / 8, 256>>>(x, ao, ln_a_g, ln_a_b, ln1, ln116);
    // FFN
    gemm_dual<1, __half><<<dim3(DFFC / 64, MM / 64, 1), 128, GEMM_SMEM>>>(
        ln116, wf116, b_ff1, h16,  ln116, wf116, b_ff1, h16, DFFC, DD, 1.0f, 1.0f);
    gemm_dual<0, float><<<dim3(4, MM / 64, 1), 128, GEMM_SMEM>>>(
        h16, wf216, b_ff2, ff,  h16, wf216, b_ff2, ff, DD, DFFC, 1.0f, 1.0f);
    // final LN
    ln_residual<0><<<MM / 8, 256>>>(ln1, ff, ln_b_g, ln_b_b, out, (__half*)nullptr);
}